// round 2
// baseline (speedup 1.0000x reference)
#include <cuda_runtime.h>
#include <cstdint>

#define SEQ   1024
#define BATCH 4
#define DM    1024
#define NH    16
#define HD    64
#define DFF   4096
#define NL    4
#define WIN   64
#define MTOT  (SEQ*BATCH)

// ---------------- scratch (no allocation allowed) ----------------
__device__ float g_xb   [MTOT * DM];        // activations [B*S, d]
__device__ float g_qkv  [MTOT * 3 * DM];    // qkv          [B*S, 3d]
__device__ float g_att  [MTOT * DM];        // attn output  [B*S, d]
__device__ float g_ff   [MTOT * DFF];       // ff hidden    [B*S, dff]
__device__ float g_delta[MTOT * DM];        // proj / ff2 out

// ---------------- layout transposes ----------------
// x [S,B,d] -> xb [B*S, d]
__global__ void k_in(const float* __restrict__ x, float* __restrict__ xb) {
    int idx = blockIdx.x * blockDim.x + threadIdx.x;
    if (idx >= MTOT * DM) return;
    int kcol = idx % DM;
    int row  = idx / DM;
    int b = row / SEQ, s = row % SEQ;
    xb[idx] = x[((size_t)(s * BATCH + b)) * DM + kcol];
}
// xb [B*S, d] -> out [S,B,d]
__global__ void k_out(const float* __restrict__ xb, float* __restrict__ out) {
    int idx = blockIdx.x * blockDim.x + threadIdx.x;
    if (idx >= MTOT * DM) return;
    int kcol = idx % DM;
    int r    = idx / DM;          // r = s*BATCH + b
    int b = r % BATCH, s = r / BATCH;
    out[idx] = xb[((size_t)(b * SEQ + s)) * DM + kcol];
}

// ---------------- SGEMM: C[M,N] = A[M,K] * B[N,K]^T + bias, opt ReLU ----------------
template<int RELU>
__global__ void __launch_bounds__(256)
k_gemm(const float* __restrict__ A, const float* __restrict__ B,
       const float* __restrict__ bias, float* __restrict__ C,
       int M, int N, int K)
{
    __shared__ float As[8][128];
    __shared__ float Bs[8][128];

    const int tid = threadIdx.x;
    const int tx = tid & 15;          // 0..15 (N dir)
    const int ty = tid >> 4;          // 0..15 (M dir)
    const int m0 = blockIdx.y * 128;
    const int n0 = blockIdx.x * 128;

    const int lrow = tid >> 1;        // 0..127
    const int lcol = (tid & 1) * 4;   // 0 or 4

    const float* Ap = A + (size_t)(m0 + lrow) * K + lcol;
    const float* Bp = B + (size_t)(n0 + lrow) * K + lcol;

    float acc[8][8];
#pragma unroll
    for (int i = 0; i < 8; i++)
#pragma unroll
        for (int j = 0; j < 8; j++) acc[i][j] = 0.f;

    for (int k0 = 0; k0 < K; k0 += 8) {
        float4 av = *(const float4*)(Ap + k0);
        float4 bv = *(const float4*)(Bp + k0);
        __syncthreads();
        As[lcol + 0][lrow] = av.x; As[lcol + 1][lrow] = av.y;
        As[lcol + 2][lrow] = av.z; As[lcol + 3][lrow] = av.w;
        Bs[lcol + 0][lrow] = bv.x; Bs[lcol + 1][lrow] = bv.y;
        Bs[lcol + 2][lrow] = bv.z; Bs[lcol + 3][lrow] = bv.w;
        __syncthreads();
#pragma unroll
        for (int k = 0; k < 8; k++) {
            float4 a0 = *(const float4*)&As[k][ty * 4];
            float4 a1 = *(const float4*)&As[k][64 + ty * 4];
            float4 b0 = *(const float4*)&Bs[k][tx * 4];
            float4 b1 = *(const float4*)&Bs[k][64 + tx * 4];
            float a[8] = {a0.x, a0.y, a0.z, a0.w, a1.x, a1.y, a1.z, a1.w};
            float b[8] = {b0.x, b0.y, b0.z, b0.w, b1.x, b1.y, b1.z, b1.w};
#pragma unroll
            for (int i = 0; i < 8; i++)
#pragma unroll
                for (int j = 0; j < 8; j++) acc[i][j] += a[i] * b[j];
        }
    }

    float4 bias0 = *(const float4*)(bias + n0 + tx * 4);
    float4 bias1 = *(const float4*)(bias + n0 + 64 + tx * 4);
    const float bb[8] = {bias0.x, bias0.y, bias0.z, bias0.w,
                         bias1.x, bias1.y, bias1.z, bias1.w};
#pragma unroll
    for (int i = 0; i < 8; i++) {
        int row = m0 + ((i < 4) ? (ty * 4 + i) : (64 + ty * 4 + i - 4));
        float v[8];
#pragma unroll
        for (int j = 0; j < 8; j++) {
            v[j] = acc[i][j] + bb[j];
            if (RELU) v[j] = fmaxf(v[j], 0.f);
        }
        float4 w0 = {v[0], v[1], v[2], v[3]};
        float4 w1 = {v[4], v[5], v[6], v[7]};
        *(float4*)(C + (size_t)row * N + n0 + tx * 4)      = w0;
        *(float4*)(C + (size_t)row * N + n0 + 64 + tx * 4) = w1;
    }
}

// ---------------- banded attention (j <= q + WIN), flash-style ----------------
// grid (qtile=16, head=16, batch=4), 64 threads; thread t owns query q = qt*64+t
__global__ void __launch_bounds__(64)
k_attn(const float* __restrict__ qkv, float* __restrict__ att)
{
    __shared__ float Qt[64][64];   // [k][q]  (transposed Q tile)
    __shared__ float KV[64][64];   // K chunk then V chunk [j][k/d]
    __shared__ float Ps[64][64];   // probabilities [j][q]

    const int t  = threadIdx.x;
    const int qt = blockIdx.x, h = blockIdx.y, b = blockIdx.z;
    const int q  = qt * 64 + t;
    const int nch = min(16, qt + 2);
    const size_t rstride = 3 * DM;
    const int lr = t >> 4;              // 0..3
    const int lc = (t & 15) * 4;        // 0..60

    // load Q tile transposed (coalesced gmem, scalar smem stores)
    for (int step = 0; step < 16; step++) {
        int rr = step * 4 + lr;
        float4 v = *(const float4*)(qkv + (size_t)(b * SEQ + qt * 64 + rr) * rstride + h * HD + lc);
        Qt[lc + 0][rr] = v.x; Qt[lc + 1][rr] = v.y;
        Qt[lc + 2][rr] = v.z; Qt[lc + 3][rr] = v.w;
    }

    float o[64];
#pragma unroll
    for (int d = 0; d < 64; d++) o[d] = 0.f;
    float mrow = -1e30f, lrow = 0.f;

    for (int c = 0; c < nch; c++) {
        __syncthreads();
        // load K chunk (coalesced)
        for (int step = 0; step < 16; step++) {
            int rr = step * 4 + lr;
            *(float4*)&KV[rr][lc] =
                *(const float4*)(qkv + (size_t)(b * SEQ + c * 64 + rr) * rstride + DM + h * HD + lc);
        }
        __syncthreads();

        // scores: s[j] = Q[q,:] . K[j,:]
        float s[64];
#pragma unroll
        for (int j = 0; j < 64; j++) s[j] = 0.f;
        for (int k = 0; k < 64; k++) {
            float qv = Qt[k][t];
#pragma unroll
            for (int j = 0; j < 64; j++) s[j] += qv * KV[j][k];
        }

        const float scale = 0.125f;   // 1/sqrt(64)
        float mc = -1e30f;
#pragma unroll
        for (int j = 0; j < 64; j++) {
            int jg = c * 64 + j;
            float sv = (jg <= q + WIN) ? s[j] * scale : -1e30f;
            s[j] = sv;
            mc = fmaxf(mc, sv);
        }
        float mnew  = fmaxf(mrow, mc);
        float alpha = __expf(mrow - mnew);
        lrow *= alpha;
#pragma unroll
        for (int d = 0; d < 64; d++) o[d] *= alpha;
#pragma unroll
        for (int j = 0; j < 64; j++) {
            float p = __expf(s[j] - mnew);
            lrow += p;
            Ps[j][t] = p;
        }
        mrow = mnew;

        __syncthreads();
        // load V chunk over K (coalesced)
        for (int step = 0; step < 16; step++) {
            int rr = step * 4 + lr;
            *(float4*)&KV[rr][lc] =
                *(const float4*)(qkv + (size_t)(b * SEQ + c * 64 + rr) * rstride + 2 * DM + h * HD + lc);
        }
        __syncthreads();

        // o += P . V
        for (int j = 0; j < 64; j++) {
            float p = Ps[j][t];
#pragma unroll
            for (int d = 0; d < 64; d++) o[d] += p * KV[j][d];
        }
    }

    float inv = 1.0f / lrow;
    float* orow = att + (size_t)(b * SEQ + q) * DM + h * HD;
#pragma unroll
    for (int d = 0; d < 64; d += 4) {
        float4 w = {o[d] * inv, o[d + 1] * inv, o[d + 2] * inv, o[d + 3] * inv};
        *(float4*)(orow + d) = w;
    }
}

// ---------------- LayerNorm(resid + delta) ----------------
__global__ void __launch_bounds__(256)
k_ln(const float* __restrict__ resid, const float* __restrict__ delta,
     const float* __restrict__ gamma, const float* __restrict__ beta,
     float* __restrict__ out)
{
    __shared__ float red[8];
    const int row = blockIdx.x;
    const int t = threadIdx.x;
    const float* rp = resid + (size_t)row * DM;
    const float* dp = delta + (size_t)row * DM;

    float4 rv = *(const float4*)(rp + t * 4);
    float4 dv = *(const float4*)(dp + t * 4);
    float v[4] = {rv.x + dv.x, rv.y + dv.y, rv.z + dv.z, rv.w + dv.w};

    float s = v[0] + v[1] + v[2] + v[3];
#pragma unroll
    for (int off = 16; off; off >>= 1) s += __shfl_xor_sync(~0u, s, off);
    if ((t & 31) == 0) red[t >> 5] = s;
    __syncthreads();
    if (t < 8) {
        float x = red[t];
#pragma unroll
        for (int off = 4; off; off >>= 1) x += __shfl_xor_sync(0xffu, x, off);
        if (t == 0) red[0] = x;
    }
    __syncthreads();
    float mu = red[0] * (1.0f / DM);
    __syncthreads();

    float vs = 0.f;
#pragma unroll
    for (int i = 0; i < 4; i++) { float d = v[i] - mu; vs += d * d; }
#pragma unroll
    for (int off = 16; off; off >>= 1) vs += __shfl_xor_sync(~0u, vs, off);
    if ((t & 31) == 0) red[t >> 5] = vs;
    __syncthreads();
    if (t < 8) {
        float x = red[t];
#pragma unroll
        for (int off = 4; off; off >>= 1) x += __shfl_xor_sync(0xffu, x, off);
        if (t == 0) red[0] = x;
    }
    __syncthreads();
    float rstd = rsqrtf(red[0] * (1.0f / DM) + 1e-5f);

    float4 g4 = *(const float4*)(gamma + t * 4);
    float4 b4 = *(const float4*)(beta  + t * 4);
    float4 w;
    w.x = (v[0] - mu) * rstd * g4.x + b4.x;
    w.y = (v[1] - mu) * rstd * g4.y + b4.y;
    w.z = (v[2] - mu) * rstd * g4.z + b4.z;
    w.w = (v[3] - mu) * rstd * g4.w + b4.w;
    *(float4*)(out + (size_t)row * DM + t * 4) = w;
}

// ---------------- host driver ----------------
extern "C" void kernel_launch(void* const* d_in, const int* in_sizes, int n_in,
                              void* d_out, int out_size)
{
    const float* x    = (const float*)d_in[0];
    const float* Wqkv = (const float*)d_in[1];
    const float* bqkv = (const float*)d_in[2];
    const float* Wo   = (const float*)d_in[3];
    const float* bo   = (const float*)d_in[4];
    const float* W1   = (const float*)d_in[5];
    const float* b1   = (const float*)d_in[6];
    const float* W2   = (const float*)d_in[7];
    const float* b2   = (const float*)d_in[8];
    const float* g1   = (const float*)d_in[9];
    const float* be1  = (const float*)d_in[10];
    const float* g2   = (const float*)d_in[11];
    const float* be2  = (const float*)d_in[12];
    float* out = (float*)d_out;

    float *p_xb, *p_qkv, *p_att, *p_ff, *p_delta;
    cudaGetSymbolAddress((void**)&p_xb,    g_xb);
    cudaGetSymbolAddress((void**)&p_qkv,   g_qkv);
    cudaGetSymbolAddress((void**)&p_att,   g_att);
    cudaGetSymbolAddress((void**)&p_ff,    g_ff);
    cudaGetSymbolAddress((void**)&p_delta, g_delta);

    const int nElem = MTOT * DM;
    k_in<<<(nElem + 255) / 256, 256>>>(x, p_xb);

    for (int l = 0; l < NL; l++) {
        // QKV projection: [M,3d] = xb * Wqkv^T + bqkv
        k_gemm<0><<<dim3(3 * DM / 128, MTOT / 128), 256>>>(
            p_xb, Wqkv + (size_t)l * 3 * DM * DM, bqkv + (size_t)l * 3 * DM,
            p_qkv, MTOT, 3 * DM, DM);

        // attention
        k_attn<<<dim3(SEQ / 64, NH, BATCH), 64>>>(p_qkv, p_att);

        // output projection
        k_gemm<0><<<dim3(DM / 128, MTOT / 128), 256>>>(
            p_att, Wo + (size_t)l * DM * DM, bo + (size_t)l * DM,
            p_delta, MTOT, DM, DM);

        // xb = LN(xb + delta)
        k_ln<<<MTOT, 256>>>(p_xb, p_delta, g1 + (size_t)l * DM, be1 + (size_t)l * DM, p_xb);

        // FF1 + ReLU
        k_gemm<1><<<dim3(DFF / 128, MTOT / 128), 256>>>(
            p_xb, W1 + (size_t)l * DFF * DM, b1 + (size_t)l * DFF,
            p_ff, MTOT, DFF, DM);

        // FF2
        k_gemm<0><<<dim3(DM / 128, MTOT / 128), 256>>>(
            p_ff, W2 + (size_t)l * DM * DFF, b2 + (size_t)l * DM,
            p_delta, MTOT, DM, DFF);

        // xb = LN(xb + delta)
        k_ln<<<MTOT, 256>>>(p_xb, p_delta, g2 + (size_t)l * DM, be2 + (size_t)l * DM, p_xb);
    }

    k_out<<<(nElem + 255) / 256, 256>>>(p_xb, out);
}

// round 3
// speedup vs baseline: 1.0005x; 1.0005x over previous
#include <cuda_runtime.h>
#include <cstdint>

#define SEQ   1024
#define BATCH 4
#define DM    1024
#define NH    16
#define HD    64
#define DFF   4096
#define NL    4
#define WIN   64
#define MTOT  (SEQ*BATCH)

// ---------------- scratch (no allocation allowed) ----------------
__device__ float g_xb   [MTOT * DM];        // activations [B*S, d]
__device__ float g_qkv  [MTOT * 3 * DM];    // qkv          [B*S, 3d]
__device__ float g_att  [MTOT * DM];        // attn output  [B*S, d]
__device__ float g_ff   [MTOT * DFF];       // ff hidden    [B*S, dff]
__device__ float g_delta[MTOT * DM];        // proj / ff2 out

// ---------------- layout transposes ----------------
// x [S,B,d] -> xb [B*S, d]
__global__ void k_in(const float* __restrict__ x, float* __restrict__ xb) {
    int idx = blockIdx.x * blockDim.x + threadIdx.x;
    if (idx >= MTOT * DM) return;
    int kcol = idx % DM;
    int row  = idx / DM;
    int b = row / SEQ, s = row % SEQ;
    xb[idx] = x[((size_t)(s * BATCH + b)) * DM + kcol];
}
// xb [B*S, d] -> out [S,B,d]
__global__ void k_out(const float* __restrict__ xb, float* __restrict__ out) {
    int idx = blockIdx.x * blockDim.x + threadIdx.x;
    if (idx >= MTOT * DM) return;
    int kcol = idx % DM;
    int r    = idx / DM;          // r = s*BATCH + b
    int b = r % BATCH, s = r / BATCH;
    out[idx] = xb[((size_t)(b * SEQ + s)) * DM + kcol];
}

// ---------------- SGEMM: C[M,N] = A[M,K] * B[N,K]^T + bias, opt ReLU ----------------
template<int RELU>
__global__ void __launch_bounds__(256)
k_gemm(const float* __restrict__ A, const float* __restrict__ B,
       const float* __restrict__ bias, float* __restrict__ C,
       int M, int N, int K)
{
    __shared__ float As[8][128];
    __shared__ float Bs[8][128];

    const int tid = threadIdx.x;
    const int tx = tid & 15;          // 0..15 (N dir)
    const int ty = tid >> 4;          // 0..15 (M dir)
    const int m0 = blockIdx.y * 128;
    const int n0 = blockIdx.x * 128;

    const int lrow = tid >> 1;        // 0..127
    const int lcol = (tid & 1) * 4;   // 0 or 4

    const float* Ap = A + (size_t)(m0 + lrow) * K + lcol;
    const float* Bp = B + (size_t)(n0 + lrow) * K + lcol;

    float acc[8][8];
#pragma unroll
    for (int i = 0; i < 8; i++)
#pragma unroll
        for (int j = 0; j < 8; j++) acc[i][j] = 0.f;

    for (int k0 = 0; k0 < K; k0 += 8) {
        float4 av = *(const float4*)(Ap + k0);
        float4 bv = *(const float4*)(Bp + k0);
        __syncthreads();
        As[lcol + 0][lrow] = av.x; As[lcol + 1][lrow] = av.y;
        As[lcol + 2][lrow] = av.z; As[lcol + 3][lrow] = av.w;
        Bs[lcol + 0][lrow] = bv.x; Bs[lcol + 1][lrow] = bv.y;
        Bs[lcol + 2][lrow] = bv.z; Bs[lcol + 3][lrow] = bv.w;
        __syncthreads();
#pragma unroll
        for (int k = 0; k < 8; k++) {
            float4 a0 = *(const float4*)&As[k][ty * 4];
            float4 a1 = *(const float4*)&As[k][64 + ty * 4];
            float4 b0 = *(const float4*)&Bs[k][tx * 4];
            float4 b1 = *(const float4*)&Bs[k][64 + tx * 4];
            float a[8] = {a0.x, a0.y, a0.z, a0.w, a1.x, a1.y, a1.z, a1.w};
            float b[8] = {b0.x, b0.y, b0.z, b0.w, b1.x, b1.y, b1.z, b1.w};
#pragma unroll
            for (int i = 0; i < 8; i++)
#pragma unroll
                for (int j = 0; j < 8; j++) acc[i][j] += a[i] * b[j];
        }
    }

    float4 bias0 = *(const float4*)(bias + n0 + tx * 4);
    float4 bias1 = *(const float4*)(bias + n0 + 64 + tx * 4);
    const float bb[8] = {bias0.x, bias0.y, bias0.z, bias0.w,
                         bias1.x, bias1.y, bias1.z, bias1.w};
#pragma unroll
    for (int i = 0; i < 8; i++) {
        int row = m0 + ((i < 4) ? (ty * 4 + i) : (64 + ty * 4 + i - 4));
        float v[8];
#pragma unroll
        for (int j = 0; j < 8; j++) {
            v[j] = acc[i][j] + bb[j];
            if (RELU) v[j] = fmaxf(v[j], 0.f);
        }
        float4 w0 = {v[0], v[1], v[2], v[3]};
        float4 w1 = {v[4], v[5], v[6], v[7]};
        *(float4*)(C + (size_t)row * N + n0 + tx * 4)      = w0;
        *(float4*)(C + (size_t)row * N + n0 + 64 + tx * 4) = w1;
    }
}

// ---------------- banded attention (j <= q + WIN), flash-style ----------------
// grid (qtile=16, head=16, batch=4), 64 threads; thread t owns query q = qt*64+t
__global__ void __launch_bounds__(64)
k_attn(const float* __restrict__ qkv, float* __restrict__ att)
{
    __shared__ float Qt[64][64];   // [k][q]  (transposed Q tile)
    __shared__ float KV[64][64];   // K chunk then V chunk [j][k/d]
    __shared__ float Ps[64][64];   // probabilities [j][q]

    const int t  = threadIdx.x;
    const int qt = blockIdx.x, h = blockIdx.y, b = blockIdx.z;
    const int q  = qt * 64 + t;
    const int nch = min(16, qt + 2);
    const size_t rstride = 3 * DM;
    const int lr = t >> 4;              // 0..3
    const int lc = (t & 15) * 4;        // 0..60

    // load Q tile transposed (coalesced gmem, scalar smem stores)
    for (int step = 0; step < 16; step++) {
        int rr = step * 4 + lr;
        float4 v = *(const float4*)(qkv + (size_t)(b * SEQ + qt * 64 + rr) * rstride + h * HD + lc);
        Qt[lc + 0][rr] = v.x; Qt[lc + 1][rr] = v.y;
        Qt[lc + 2][rr] = v.z; Qt[lc + 3][rr] = v.w;
    }

    float o[64];
#pragma unroll
    for (int d = 0; d < 64; d++) o[d] = 0.f;
    float mrow = -1e30f, lrow = 0.f;

    for (int c = 0; c < nch; c++) {
        __syncthreads();
        // load K chunk (coalesced)
        for (int step = 0; step < 16; step++) {
            int rr = step * 4 + lr;
            *(float4*)&KV[rr][lc] =
                *(const float4*)(qkv + (size_t)(b * SEQ + c * 64 + rr) * rstride + DM + h * HD + lc);
        }
        __syncthreads();

        // scores: s[j] = Q[q,:] . K[j,:]
        float s[64];
#pragma unroll
        for (int j = 0; j < 64; j++) s[j] = 0.f;
        for (int k = 0; k < 64; k++) {
            float qv = Qt[k][t];
#pragma unroll
            for (int j = 0; j < 64; j++) s[j] += qv * KV[j][k];
        }

        const float scale = 0.125f;   // 1/sqrt(64)
        float mc = -1e30f;
#pragma unroll
        for (int j = 0; j < 64; j++) {
            int jg = c * 64 + j;
            float sv = (jg <= q + WIN) ? s[j] * scale : -1e30f;
            s[j] = sv;
            mc = fmaxf(mc, sv);
        }
        float mnew  = fmaxf(mrow, mc);
        float alpha = __expf(mrow - mnew);
        lrow *= alpha;
#pragma unroll
        for (int d = 0; d < 64; d++) o[d] *= alpha;
#pragma unroll
        for (int j = 0; j < 64; j++) {
            float p = __expf(s[j] - mnew);
            lrow += p;
            Ps[j][t] = p;
        }
        mrow = mnew;

        __syncthreads();
        // load V chunk over K (coalesced)
        for (int step = 0; step < 16; step++) {
            int rr = step * 4 + lr;
            *(float4*)&KV[rr][lc] =
                *(const float4*)(qkv + (size_t)(b * SEQ + c * 64 + rr) * rstride + 2 * DM + h * HD + lc);
        }
        __syncthreads();

        // o += P . V
        for (int j = 0; j < 64; j++) {
            float p = Ps[j][t];
#pragma unroll
            for (int d = 0; d < 64; d++) o[d] += p * KV[j][d];
        }
    }

    float inv = 1.0f / lrow;
    float* orow = att + (size_t)(b * SEQ + q) * DM + h * HD;
#pragma unroll
    for (int d = 0; d < 64; d += 4) {
        float4 w = {o[d] * inv, o[d + 1] * inv, o[d + 2] * inv, o[d + 3] * inv};
        *(float4*)(orow + d) = w;
    }
}

// ---------------- LayerNorm(resid + delta) ----------------
__global__ void __launch_bounds__(256)
k_ln(const float* __restrict__ resid, const float* __restrict__ delta,
     const float* __restrict__ gamma, const float* __restrict__ beta,
     float* __restrict__ out)
{
    __shared__ float red[8];
    const int row = blockIdx.x;
    const int t = threadIdx.x;
    const float* rp = resid + (size_t)row * DM;
    const float* dp = delta + (size_t)row * DM;

    float4 rv = *(const float4*)(rp + t * 4);
    float4 dv = *(const float4*)(dp + t * 4);
    float v[4] = {rv.x + dv.x, rv.y + dv.y, rv.z + dv.z, rv.w + dv.w};

    float s = v[0] + v[1] + v[2] + v[3];
#pragma unroll
    for (int off = 16; off; off >>= 1) s += __shfl_xor_sync(~0u, s, off);
    if ((t & 31) == 0) red[t >> 5] = s;
    __syncthreads();
    if (t < 8) {
        float x = red[t];
#pragma unroll
        for (int off = 4; off; off >>= 1) x += __shfl_xor_sync(0xffu, x, off);
        if (t == 0) red[0] = x;
    }
    __syncthreads();
    float mu = red[0] * (1.0f / DM);
    __syncthreads();

    float vs = 0.f;
#pragma unroll
    for (int i = 0; i < 4; i++) { float d = v[i] - mu; vs += d * d; }
#pragma unroll
    for (int off = 16; off; off >>= 1) vs += __shfl_xor_sync(~0u, vs, off);
    if ((t & 31) == 0) red[t >> 5] = vs;
    __syncthreads();
    if (t < 8) {
        float x = red[t];
#pragma unroll
        for (int off = 4; off; off >>= 1) x += __shfl_xor_sync(0xffu, x, off);
        if (t == 0) red[0] = x;
    }
    __syncthreads();
    float rstd = rsqrtf(red[0] * (1.0f / DM) + 1e-5f);

    float4 g4 = *(const float4*)(gamma + t * 4);
    float4 b4 = *(const float4*)(beta  + t * 4);
    float4 w;
    w.x = (v[0] - mu) * rstd * g4.x + b4.x;
    w.y = (v[1] - mu) * rstd * g4.y + b4.y;
    w.z = (v[2] - mu) * rstd * g4.z + b4.z;
    w.w = (v[3] - mu) * rstd * g4.w + b4.w;
    *(float4*)(out + (size_t)row * DM + t * 4) = w;
}

// ---------------- host driver ----------------
extern "C" void kernel_launch(void* const* d_in, const int* in_sizes, int n_in,
                              void* d_out, int out_size)
{
    const float* x    = (const float*)d_in[0];
    const float* Wqkv = (const float*)d_in[1];
    const float* bqkv = (const float*)d_in[2];
    const float* Wo   = (const float*)d_in[3];
    const float* bo   = (const float*)d_in[4];
    const float* W1   = (const float*)d_in[5];
    const float* b1   = (const float*)d_in[6];
    const float* W2   = (const float*)d_in[7];
    const float* b2   = (const float*)d_in[8];
    const float* g1   = (const float*)d_in[9];
    const float* be1  = (const float*)d_in[10];
    const float* g2   = (const float*)d_in[11];
    const float* be2  = (const float*)d_in[12];
    float* out = (float*)d_out;

    float *p_xb, *p_qkv, *p_att, *p_ff, *p_delta;
    cudaGetSymbolAddress((void**)&p_xb,    g_xb);
    cudaGetSymbolAddress((void**)&p_qkv,   g_qkv);
    cudaGetSymbolAddress((void**)&p_att,   g_att);
    cudaGetSymbolAddress((void**)&p_ff,    g_ff);
    cudaGetSymbolAddress((void**)&p_delta, g_delta);

    const int nElem = MTOT * DM;
    k_in<<<(nElem + 255) / 256, 256>>>(x, p_xb);

    for (int l = 0; l < NL; l++) {
        // QKV projection: [M,3d] = xb * Wqkv^T + bqkv
        k_gemm<0><<<dim3(3 * DM / 128, MTOT / 128), 256>>>(
            p_xb, Wqkv + (size_t)l * 3 * DM * DM, bqkv + (size_t)l * 3 * DM,
            p_qkv, MTOT, 3 * DM, DM);

        // attention
        k_attn<<<dim3(SEQ / 64, NH, BATCH), 64>>>(p_qkv, p_att);

        // output projection
        k_gemm<0><<<dim3(DM / 128, MTOT / 128), 256>>>(
            p_att, Wo + (size_t)l * DM * DM, bo + (size_t)l * DM,
            p_delta, MTOT, DM, DM);

        // xb = LN(xb + delta)
        k_ln<<<MTOT, 256>>>(p_xb, p_delta, g1 + (size_t)l * DM, be1 + (size_t)l * DM, p_xb);

        // FF1 + ReLU
        k_gemm<1><<<dim3(DFF / 128, MTOT / 128), 256>>>(
            p_xb, W1 + (size_t)l * DFF * DM, b1 + (size_t)l * DFF,
            p_ff, MTOT, DFF, DM);

        // FF2
        k_gemm<0><<<dim3(DM / 128, MTOT / 128), 256>>>(
            p_ff, W2 + (size_t)l * DM * DFF, b2 + (size_t)l * DM,
            p_delta, MTOT, DM, DFF);

        // xb = LN(xb + delta)
        k_ln<<<MTOT, 256>>>(p_xb, p_delta, g2 + (size_t)l * DM, be2 + (size_t)l * DM, p_xb);
    }

    k_out<<<(nElem + 255) / 256, 256>>>(p_xb, out);
}

// round 5
// speedup vs baseline: 1.7982x; 1.7973x over previous
#include <cuda_runtime.h>
#include <cuda_bf16.h>
#include <cstdint>

#define SEQ   1024
#define BATCH 4
#define DM    1024
#define NH    16
#define HD    64
#define DFF   4096
#define NL    4
#define WIN   64
#define MTOT  (SEQ*BATCH)

// ======================= PTX helpers (sm_80+ features only) =======================
__device__ __forceinline__ uint32_t smem_to_u32(const void* p) {
    uint32_t a;
    asm("{ .reg .u64 t; cvta.to.shared.u64 t, %1; cvt.u32.u64 %0, t; }" : "=r"(a) : "l"(p));
    return a;
}
__device__ __forceinline__ void cpa16(uint32_t smem, const void* gmem) {
    asm volatile("cp.async.cg.shared.global [%0], [%1], 16;" :: "r"(smem), "l"(gmem) : "memory");
}
__device__ __forceinline__ void ldsm_x4(uint32_t* r, uint32_t addr) {
    asm volatile("ldmatrix.sync.aligned.m8n8.x4.shared.b16 {%0,%1,%2,%3}, [%4];"
        : "=r"(r[0]), "=r"(r[1]), "=r"(r[2]), "=r"(r[3]) : "r"(addr));
}
__device__ __forceinline__ void ldsm_x2(uint32_t* r, uint32_t addr) {
    asm volatile("ldmatrix.sync.aligned.m8n8.x2.shared.b16 {%0,%1}, [%2];"
        : "=r"(r[0]), "=r"(r[1]) : "r"(addr));
}
__device__ __forceinline__ void mma16816(float* c, const uint32_t* a, const uint32_t* b) {
    asm volatile(
        "mma.sync.aligned.m16n8k16.row.col.f32.bf16.bf16.f32 "
        "{%0,%1,%2,%3}, {%4,%5,%6,%7}, {%8,%9}, {%0,%1,%2,%3};"
        : "+f"(c[0]), "+f"(c[1]), "+f"(c[2]), "+f"(c[3])
        : "r"(a[0]), "r"(a[1]), "r"(a[2]), "r"(a[3]), "r"(b[0]), "r"(b[1]));
}

// ======================= scratch (device globals) =======================
__device__ __align__(256) float          g_xb   [MTOT * DM];
__device__ __align__(256) __nv_bfloat16  g_xh   [MTOT * DM];
__device__ __align__(256) __nv_bfloat16  g_xl   [MTOT * DM];
__device__ __align__(256) float          g_qkv  [MTOT * 3 * DM];
__device__ __align__(256) __nv_bfloat16  g_ah   [MTOT * DM];
__device__ __align__(256) __nv_bfloat16  g_al   [MTOT * DM];
__device__ __align__(256) float          g_delta[MTOT * DM];
__device__ __align__(256) __nv_bfloat16  g_fh   [MTOT * DFF];
__device__ __align__(256) __nv_bfloat16  g_fl   [MTOT * DFF];
__device__ __align__(256) __nv_bfloat16  g_wqh  [NL * 3 * DM * DM];
__device__ __align__(256) __nv_bfloat16  g_wql  [NL * 3 * DM * DM];
__device__ __align__(256) __nv_bfloat16  g_woh  [NL * DM * DM];
__device__ __align__(256) __nv_bfloat16  g_wol  [NL * DM * DM];
__device__ __align__(256) __nv_bfloat16  g_w1h  [NL * DFF * DM];
__device__ __align__(256) __nv_bfloat16  g_w1l  [NL * DFF * DM];
__device__ __align__(256) __nv_bfloat16  g_w2h  [NL * DM * DFF];
__device__ __align__(256) __nv_bfloat16  g_w2l  [NL * DM * DFF];

__device__ __forceinline__ void split1(float v, __nv_bfloat16& h, __nv_bfloat16& l) {
    h = __float2bfloat16(v);
    l = __float2bfloat16(v - __bfloat162float(h));
}

// ======================= elementwise kernels =======================
__global__ void k_split(const float* __restrict__ s, __nv_bfloat16* __restrict__ h,
                        __nv_bfloat16* __restrict__ l, int n4) {
    int i = blockIdx.x * blockDim.x + threadIdx.x;
    if (i >= n4) return;
    float4 v = *(const float4*)(s + (size_t)i * 4);
    __nv_bfloat16 h0, h1, h2, h3, l0, l1, l2, l3;
    split1(v.x, h0, l0); split1(v.y, h1, l1); split1(v.z, h2, l2); split1(v.w, h3, l3);
    __nv_bfloat162 hh0; hh0.x = h0; hh0.y = h1;
    __nv_bfloat162 hh1; hh1.x = h2; hh1.y = h3;
    __nv_bfloat162 ll0; ll0.x = l0; ll0.y = l1;
    __nv_bfloat162 ll1; ll1.x = l2; ll1.y = l3;
    *(__nv_bfloat162*)(h + (size_t)i * 4)     = hh0;
    *(__nv_bfloat162*)(h + (size_t)i * 4 + 2) = hh1;
    *(__nv_bfloat162*)(l + (size_t)i * 4)     = ll0;
    *(__nv_bfloat162*)(l + (size_t)i * 4 + 2) = ll1;
}

__global__ void k_in(const float* __restrict__ x, float* __restrict__ xb,
                     __nv_bfloat16* __restrict__ xh, __nv_bfloat16* __restrict__ xl) {
    int idx = blockIdx.x * blockDim.x + threadIdx.x;
    if (idx >= MTOT * DM) return;
    int kcol = idx % DM;
    int row  = idx / DM;
    int b = row / SEQ, s = row % SEQ;
    float v = x[((size_t)(s * BATCH + b)) * DM + kcol];
    xb[idx] = v;
    __nv_bfloat16 h, l; split1(v, h, l);
    xh[idx] = h; xl[idx] = l;
}

__global__ void k_out(const float* __restrict__ xb, float* __restrict__ out) {
    int idx = blockIdx.x * blockDim.x + threadIdx.x;
    if (idx >= MTOT * DM) return;
    int kcol = idx % DM;
    int r    = idx / DM;
    int b = r % BATCH, s = r / BATCH;
    out[idx] = xb[((size_t)(b * SEQ + s)) * DM + kcol];
}

// ======================= HMMA GEMM (mma.sync bf16, 3-term split) =======================
// C[M,N] = A[M,K]*B[N,K]^T (+bias, opt relu/split-out). A,B as bf16 hi/lo.
// Block 128x128, K-chunk 64, 2-stage cp.async double buffer.
#define PAD    72                           // bf16 elements per row in smem
#define TILE_B (128 * PAD * 2)              // 18432 B
#define STGB   (4 * TILE_B)                 // Ah,Al,Bh,Bl per stage
#define TG_SMEM (2 * STGB)                  // 147456 B

template<int RELU, int SPLIT>
__global__ void __launch_bounds__(256, 1)
k_tgemm(const __nv_bfloat16* __restrict__ Ah, const __nv_bfloat16* __restrict__ Al,
        const __nv_bfloat16* __restrict__ Bh, const __nv_bfloat16* __restrict__ Bl,
        const float* __restrict__ bias,
        float* __restrict__ Cf, __nv_bfloat16* __restrict__ Ch, __nv_bfloat16* __restrict__ Cl,
        int M, int N, int K)
{
    extern __shared__ char dsm[];
    const uint32_t sbase = smem_to_u32(dsm);
    const int tid  = threadIdx.x;
    const int lane = tid & 31;
    const int wid  = tid >> 5;
    const int wm   = wid >> 2;          // 0..1  (64-row slab)
    const int wn   = wid & 3;           // 0..3  (32-col slab)
    const int m0 = blockIdx.y * 128;
    const int n0 = blockIdx.x * 128;
    const int nch = K >> 6;

    const __nv_bfloat16* srcs[4] = {Ah, Al, Bh, Bl};
    const int rowbase[4] = {m0, m0, n0, n0};

    float acc[4][4][4];
#pragma unroll
    for (int mt = 0; mt < 4; mt++)
#pragma unroll
        for (int nt = 0; nt < 4; nt++)
#pragma unroll
            for (int i = 0; i < 4; i++) acc[mt][nt][i] = 0.f;

    // ldmatrix per-lane offsets (bytes)
    const uint32_t aoff = ((wm * 64 + (lane & 15)) * PAD + (lane >> 4) * 8) * 2;
    const uint32_t boff = ((wn * 32 + (lane & 7)) * PAD + ((lane >> 3) & 1) * 8) * 2;

    // prologue: chunk 0 -> stage 0
#pragma unroll
    for (int i = 0; i < 16; i++) {
        int idx = tid + i * 256;
        int t = idx >> 10, r = (idx & 1023) >> 3, c = idx & 7;
        cpa16(sbase + t * TILE_B + r * (PAD * 2) + c * 16,
              srcs[t] + (size_t)(rowbase[t] + r) * K + c * 8);
    }
    asm volatile("cp.async.commit_group;" ::: "memory");

    const int tA[3] = {0, 0, 1};
    const int tB[3] = {2, 3, 2};

    for (int cch = 0; cch < nch; cch++) {
        // issue loads for next chunk into other stage
        if (cch + 1 < nch) {
            uint32_t stg = sbase + ((cch + 1) & 1) * STGB;
#pragma unroll
            for (int i = 0; i < 16; i++) {
                int idx = tid + i * 256;
                int t = idx >> 10, r = (idx & 1023) >> 3, c = idx & 7;
                cpa16(stg + t * TILE_B + r * (PAD * 2) + c * 16,
                      srcs[t] + (size_t)(rowbase[t] + r) * K + (cch + 1) * 64 + c * 8);
            }
        }
        asm volatile("cp.async.commit_group;" ::: "memory");
        asm volatile("cp.async.wait_group 1;" ::: "memory");
        __syncthreads();

        const uint32_t stg = sbase + (cch & 1) * STGB;
#pragma unroll
        for (int seg = 0; seg < 3; seg++) {
            const uint32_t Ab = stg + tA[seg] * TILE_B + aoff;
            const uint32_t Bb = stg + tB[seg] * TILE_B + boff;
#pragma unroll
            for (int ks = 0; ks < 4; ks++) {
                uint32_t a[4][4], b[4][2];
#pragma unroll
                for (int mt = 0; mt < 4; mt++)
                    ldsm_x4(a[mt], Ab + (mt * 16 * PAD + ks * 16) * 2);
#pragma unroll
                for (int nt = 0; nt < 4; nt++)
                    ldsm_x2(b[nt], Bb + (nt * 8 * PAD + ks * 16) * 2);
#pragma unroll
                for (int mt = 0; mt < 4; mt++)
#pragma unroll
                    for (int nt = 0; nt < 4; nt++)
                        mma16816(acc[mt][nt], a[mt], b[nt]);
            }
        }
        __syncthreads();
    }

    // epilogue
    const int r0 = m0 + wm * 64 + (lane >> 2);
    const int c0 = n0 + wn * 32 + 2 * (lane & 3);
#pragma unroll
    for (int mt = 0; mt < 4; mt++) {
#pragma unroll
        for (int nt = 0; nt < 4; nt++) {
            int col = c0 + nt * 8;
            float b0 = bias[col], b1 = bias[col + 1];
#pragma unroll
            for (int half = 0; half < 2; half++) {
                int row = r0 + mt * 16 + half * 8;
                float v0 = acc[mt][nt][2 * half + 0] + b0;
                float v1 = acc[mt][nt][2 * half + 1] + b1;
                if (RELU) { v0 = fmaxf(v0, 0.f); v1 = fmaxf(v1, 0.f); }
                size_t off = (size_t)row * N + col;
                if (!SPLIT) {
                    float2 w = {v0, v1};
                    *(float2*)(Cf + off) = w;
                } else {
                    __nv_bfloat16 h0, l0, h1, l1;
                    split1(v0, h0, l0); split1(v1, h1, l1);
                    __nv_bfloat162 hh; hh.x = h0; hh.y = h1;
                    __nv_bfloat162 ll; ll.x = l0; ll.y = l1;
                    *(__nv_bfloat162*)(Ch + off) = hh;
                    *(__nv_bfloat162*)(Cl + off) = ll;
                }
            }
        }
    }
}

// ======================= banded attention (fp32, flash-style) =======================
__global__ void __launch_bounds__(64)
k_attn(const float* __restrict__ qkv, __nv_bfloat16* __restrict__ ah, __nv_bfloat16* __restrict__ al)
{
    __shared__ float Qt[64][64];
    __shared__ float KV[64][64];
    __shared__ float Ps[64][64];

    const int t  = threadIdx.x;
    const int qt = blockIdx.x, h = blockIdx.y, b = blockIdx.z;
    const int q  = qt * 64 + t;
    const int nch = min(16, qt + 2);
    const size_t rstride = 3 * DM;
    const int lr = t >> 4;
    const int lc = (t & 15) * 4;

    for (int step = 0; step < 16; step++) {
        int rr = step * 4 + lr;
        float4 v = *(const float4*)(qkv + (size_t)(b * SEQ + qt * 64 + rr) * rstride + h * HD + lc);
        Qt[lc + 0][rr] = v.x; Qt[lc + 1][rr] = v.y;
        Qt[lc + 2][rr] = v.z; Qt[lc + 3][rr] = v.w;
    }

    float o[64];
#pragma unroll
    for (int d = 0; d < 64; d++) o[d] = 0.f;
    float mrow = -1e30f, lrow = 0.f;

    for (int c = 0; c < nch; c++) {
        __syncthreads();
        for (int step = 0; step < 16; step++) {
            int rr = step * 4 + lr;
            *(float4*)&KV[rr][lc] =
                *(const float4*)(qkv + (size_t)(b * SEQ + c * 64 + rr) * rstride + DM + h * HD + lc);
        }
        __syncthreads();

        float s[64];
#pragma unroll
        for (int j = 0; j < 64; j++) s[j] = 0.f;
        for (int k = 0; k < 64; k++) {
            float qv = Qt[k][t];
#pragma unroll
            for (int j = 0; j < 64; j++) s[j] += qv * KV[j][k];
        }

        const float scale = 0.125f;
        float mc = -1e30f;
#pragma unroll
        for (int j = 0; j < 64; j++) {
            int jg = c * 64 + j;
            float sv = (jg <= q + WIN) ? s[j] * scale : -1e30f;
            s[j] = sv;
            mc = fmaxf(mc, sv);
        }
        float mnew  = fmaxf(mrow, mc);
        float alpha = __expf(mrow - mnew);
        lrow *= alpha;
#pragma unroll
        for (int d = 0; d < 64; d++) o[d] *= alpha;
#pragma unroll
        for (int j = 0; j < 64; j++) {
            float p = __expf(s[j] - mnew);
            lrow += p;
            Ps[j][t] = p;
        }
        mrow = mnew;

        __syncthreads();
        for (int step = 0; step < 16; step++) {
            int rr = step * 4 + lr;
            *(float4*)&KV[rr][lc] =
                *(const float4*)(qkv + (size_t)(b * SEQ + c * 64 + rr) * rstride + 2 * DM + h * HD + lc);
        }
        __syncthreads();

        for (int j = 0; j < 64; j++) {
            float p = Ps[j][t];
#pragma unroll
            for (int d = 0; d < 64; d++) o[d] += p * KV[j][d];
        }
    }

    float inv = 1.0f / lrow;
    size_t off = (size_t)(b * SEQ + q) * DM + h * HD;
#pragma unroll
    for (int d = 0; d < 64; d += 2) {
        float v0 = o[d] * inv, v1 = o[d + 1] * inv;
        __nv_bfloat16 h0, l0, h1, l1;
        split1(v0, h0, l0); split1(v1, h1, l1);
        __nv_bfloat162 hh; hh.x = h0; hh.y = h1;
        __nv_bfloat162 ll; ll.x = l0; ll.y = l1;
        *(__nv_bfloat162*)(ah + off + d) = hh;
        *(__nv_bfloat162*)(al + off + d) = ll;
    }
}

// ======================= LayerNorm(resid + delta) -> fp32 + hi/lo =======================
__global__ void __launch_bounds__(256)
k_ln(const float* __restrict__ resid, const float* __restrict__ delta,
     const float* __restrict__ gamma, const float* __restrict__ beta,
     float* __restrict__ out, __nv_bfloat16* __restrict__ oh, __nv_bfloat16* __restrict__ ol)
{
    __shared__ float red[8];
    const int row = blockIdx.x;
    const int t = threadIdx.x;
    const float* rp = resid + (size_t)row * DM;
    const float* dp = delta + (size_t)row * DM;

    float4 rv = *(const float4*)(rp + t * 4);
    float4 dv = *(const float4*)(dp + t * 4);
    float v[4] = {rv.x + dv.x, rv.y + dv.y, rv.z + dv.z, rv.w + dv.w};

    float s = v[0] + v[1] + v[2] + v[3];
#pragma unroll
    for (int off = 16; off; off >>= 1) s += __shfl_xor_sync(~0u, s, off);
    if ((t & 31) == 0) red[t >> 5] = s;
    __syncthreads();
    if (t < 8) {
        float x = red[t];
#pragma unroll
        for (int off = 4; off; off >>= 1) x += __shfl_xor_sync(0xffu, x, off);
        if (t == 0) red[0] = x;
    }
    __syncthreads();
    float mu = red[0] * (1.0f / DM);
    __syncthreads();

    float vs = 0.f;
#pragma unroll
    for (int i = 0; i < 4; i++) { float d = v[i] - mu; vs += d * d; }
#pragma unroll
    for (int off = 16; off; off >>= 1) vs += __shfl_xor_sync(~0u, vs, off);
    if ((t & 31) == 0) red[t >> 5] = vs;
    __syncthreads();
    if (t < 8) {
        float x = red[t];
#pragma unroll
        for (int off = 4; off; off >>= 1) x += __shfl_xor_sync(0xffu, x, off);
        if (t == 0) red[0] = x;
    }
    __syncthreads();
    float rstd = rsqrtf(red[0] * (1.0f / DM) + 1e-5f);

    float4 g4 = *(const float4*)(gamma + t * 4);
    float4 b4 = *(const float4*)(beta  + t * 4);
    float w[4];
    w[0] = (v[0] - mu) * rstd * g4.x + b4.x;
    w[1] = (v[1] - mu) * rstd * g4.y + b4.y;
    w[2] = (v[2] - mu) * rstd * g4.z + b4.z;
    w[3] = (v[3] - mu) * rstd * g4.w + b4.w;
    float4 wf = {w[0], w[1], w[2], w[3]};
    *(float4*)(out + (size_t)row * DM + t * 4) = wf;

    __nv_bfloat16 h0, h1, h2, h3, l0, l1, l2, l3;
    split1(w[0], h0, l0); split1(w[1], h1, l1);
    split1(w[2], h2, l2); split1(w[3], h3, l3);
    __nv_bfloat162 hh0; hh0.x = h0; hh0.y = h1;
    __nv_bfloat162 hh1; hh1.x = h2; hh1.y = h3;
    __nv_bfloat162 ll0; ll0.x = l0; ll0.y = l1;
    __nv_bfloat162 ll1; ll1.x = l2; ll1.y = l3;
    size_t o4 = (size_t)row * DM + t * 4;
    *(__nv_bfloat162*)(oh + o4)     = hh0;
    *(__nv_bfloat162*)(oh + o4 + 2) = hh1;
    *(__nv_bfloat162*)(ol + o4)     = ll0;
    *(__nv_bfloat162*)(ol + o4 + 2) = ll1;
}

// ======================= host driver =======================
extern "C" void kernel_launch(void* const* d_in, const int* in_sizes, int n_in,
                              void* d_out, int out_size)
{
    const float* x    = (const float*)d_in[0];
    const float* Wqkv = (const float*)d_in[1];
    const float* bqkv = (const float*)d_in[2];
    const float* Wo   = (const float*)d_in[3];
    const float* bo   = (const float*)d_in[4];
    const float* W1   = (const float*)d_in[5];
    const float* b1   = (const float*)d_in[6];
    const float* W2   = (const float*)d_in[7];
    const float* b2   = (const float*)d_in[8];
    const float* g1   = (const float*)d_in[9];
    const float* be1  = (const float*)d_in[10];
    const float* g2   = (const float*)d_in[11];
    const float* be2  = (const float*)d_in[12];
    float* out = (float*)d_out;

    float *p_xb, *p_qkv, *p_delta;
    __nv_bfloat16 *p_xh, *p_xl, *p_ah, *p_al, *p_fh, *p_fl;
    __nv_bfloat16 *p_wqh, *p_wql, *p_woh, *p_wol, *p_w1h, *p_w1l, *p_w2h, *p_w2l;
    cudaGetSymbolAddress((void**)&p_xb,  g_xb);
    cudaGetSymbolAddress((void**)&p_qkv, g_qkv);
    cudaGetSymbolAddress((void**)&p_delta, g_delta);
    cudaGetSymbolAddress((void**)&p_xh,  g_xh);
    cudaGetSymbolAddress((void**)&p_xl,  g_xl);
    cudaGetSymbolAddress((void**)&p_ah,  g_ah);
    cudaGetSymbolAddress((void**)&p_al,  g_al);
    cudaGetSymbolAddress((void**)&p_fh,  g_fh);
    cudaGetSymbolAddress((void**)&p_fl,  g_fl);
    cudaGetSymbolAddress((void**)&p_wqh, g_wqh);
    cudaGetSymbolAddress((void**)&p_wql, g_wql);
    cudaGetSymbolAddress((void**)&p_woh, g_woh);
    cudaGetSymbolAddress((void**)&p_wol, g_wol);
    cudaGetSymbolAddress((void**)&p_w1h, g_w1h);
    cudaGetSymbolAddress((void**)&p_w1l, g_w1l);
    cudaGetSymbolAddress((void**)&p_w2h, g_w2h);
    cudaGetSymbolAddress((void**)&p_w2l, g_w2l);

    cudaFuncSetAttribute(k_tgemm<0,0>, cudaFuncAttributeMaxDynamicSharedMemorySize, TG_SMEM);
    cudaFuncSetAttribute(k_tgemm<1,1>, cudaFuncAttributeMaxDynamicSharedMemorySize, TG_SMEM);

    // split weights (all layers at once)
    {
        int n4;
        n4 = NL * 3 * DM * DM / 4; k_split<<<(n4 + 255) / 256, 256>>>(Wqkv, p_wqh, p_wql, n4);
        n4 = NL * DM * DM / 4;     k_split<<<(n4 + 255) / 256, 256>>>(Wo,   p_woh, p_wol, n4);
        n4 = NL * DFF * DM / 4;    k_split<<<(n4 + 255) / 256, 256>>>(W1,   p_w1h, p_w1l, n4);
        n4 = NL * DM * DFF / 4;    k_split<<<(n4 + 255) / 256, 256>>>(W2,   p_w2h, p_w2l, n4);
    }

    const int nElem = MTOT * DM;
    k_in<<<(nElem + 255) / 256, 256>>>(x, p_xb, p_xh, p_xl);

    for (int l = 0; l < NL; l++) {
        // QKV projection
        k_tgemm<0,0><<<dim3(3 * DM / 128, MTOT / 128), 256, TG_SMEM>>>(
            p_xh, p_xl,
            p_wqh + (size_t)l * 3 * DM * DM, p_wql + (size_t)l * 3 * DM * DM,
            bqkv + (size_t)l * 3 * DM,
            p_qkv, nullptr, nullptr, MTOT, 3 * DM, DM);

        // attention -> hi/lo
        k_attn<<<dim3(SEQ / 64, NH, BATCH), 64>>>(p_qkv, p_ah, p_al);

        // output projection
        k_tgemm<0,0><<<dim3(DM / 128, MTOT / 128), 256, TG_SMEM>>>(
            p_ah, p_al,
            p_woh + (size_t)l * DM * DM, p_wol + (size_t)l * DM * DM,
            bo + (size_t)l * DM,
            p_delta, nullptr, nullptr, MTOT, DM, DM);

        // xb = LN(xb + delta), also hi/lo
        k_ln<<<MTOT, 256>>>(p_xb, p_delta, g1 + (size_t)l * DM, be1 + (size_t)l * DM,
                            p_xb, p_xh, p_xl);

        // FF1 + ReLU -> hi/lo
        k_tgemm<1,1><<<dim3(DFF / 128, MTOT / 128), 256, TG_SMEM>>>(
            p_xh, p_xl,
            p_w1h + (size_t)l * DFF * DM, p_w1l + (size_t)l * DFF * DM,
            b1 + (size_t)l * DFF,
            nullptr, p_fh, p_fl, MTOT, DFF, DM);

        // FF2
        k_tgemm<0,0><<<dim3(DM / 128, MTOT / 128), 256, TG_SMEM>>>(
            p_fh, p_fl,
            p_w2h + (size_t)l * DM * DFF, p_w2l + (size_t)l * DM * DFF,
            b2 + (size_t)l * DM,
            p_delta, nullptr, nullptr, MTOT, DM, DFF);

        // xb = LN(xb + delta), also hi/lo
        k_ln<<<MTOT, 256>>>(p_xb, p_delta, g2 + (size_t)l * DM, be2 + (size_t)l * DM,
                            p_xb, p_xh, p_xl);
    }

    k_out<<<(nElem + 255) / 256, 256>>>(p_xb, out);
}

// round 6
// speedup vs baseline: 1.9277x; 1.0721x over previous
#include <cuda_runtime.h>
#include <cuda_bf16.h>
#include <cstdint>

#define SEQ   1024
#define BATCH 4
#define DM    1024
#define NH    16
#define HD    64
#define DFF   4096
#define NL    4
#define WIN   64
#define MTOT  (SEQ*BATCH)

// ======================= PTX helpers (sm_80+ features only) =======================
__device__ __forceinline__ uint32_t smem_to_u32(const void* p) {
    uint32_t a;
    asm("{ .reg .u64 t; cvta.to.shared.u64 t, %1; cvt.u32.u64 %0, t; }" : "=r"(a) : "l"(p));
    return a;
}
__device__ __forceinline__ void cpa16(uint32_t smem, const void* gmem) {
    asm volatile("cp.async.cg.shared.global [%0], [%1], 16;" :: "r"(smem), "l"(gmem) : "memory");
}
__device__ __forceinline__ void ldsm_x4(uint32_t* r, uint32_t addr) {
    asm volatile("ldmatrix.sync.aligned.m8n8.x4.shared.b16 {%0,%1,%2,%3}, [%4];"
        : "=r"(r[0]), "=r"(r[1]), "=r"(r[2]), "=r"(r[3]) : "r"(addr));
}
__device__ __forceinline__ void ldsm_x2(uint32_t* r, uint32_t addr) {
    asm volatile("ldmatrix.sync.aligned.m8n8.x2.shared.b16 {%0,%1}, [%2];"
        : "=r"(r[0]), "=r"(r[1]) : "r"(addr));
}
__device__ __forceinline__ void mma16816(float* c, const uint32_t* a, const uint32_t* b) {
    asm volatile(
        "mma.sync.aligned.m16n8k16.row.col.f32.bf16.bf16.f32 "
        "{%0,%1,%2,%3}, {%4,%5,%6,%7}, {%8,%9}, {%0,%1,%2,%3};"
        : "+f"(c[0]), "+f"(c[1]), "+f"(c[2]), "+f"(c[3])
        : "r"(a[0]), "r"(a[1]), "r"(a[2]), "r"(a[3]), "r"(b[0]), "r"(b[1]));
}

// ======================= scratch (device globals) =======================
__device__ __align__(256) float          g_xb   [MTOT * DM];
__device__ __align__(256) __nv_bfloat16  g_xh   [MTOT * DM];
__device__ __align__(256) __nv_bfloat16  g_xl   [MTOT * DM];
__device__ __align__(256) float          g_qkv  [MTOT * 3 * DM];
__device__ __align__(256) __nv_bfloat16  g_ah   [MTOT * DM];
__device__ __align__(256) __nv_bfloat16  g_al   [MTOT * DM];
__device__ __align__(256) float          g_delta[MTOT * DM];
__device__ __align__(256) __nv_bfloat16  g_fh   [MTOT * DFF];
__device__ __align__(256) __nv_bfloat16  g_fl   [MTOT * DFF];
__device__ __align__(256) __nv_bfloat16  g_wqh  [NL * 3 * DM * DM];
__device__ __align__(256) __nv_bfloat16  g_wql  [NL * 3 * DM * DM];
__device__ __align__(256) __nv_bfloat16  g_woh  [NL * DM * DM];
__device__ __align__(256) __nv_bfloat16  g_wol  [NL * DM * DM];
__device__ __align__(256) __nv_bfloat16  g_w1h  [NL * DFF * DM];
__device__ __align__(256) __nv_bfloat16  g_w1l  [NL * DFF * DM];
__device__ __align__(256) __nv_bfloat16  g_w2h  [NL * DM * DFF];
__device__ __align__(256) __nv_bfloat16  g_w2l  [NL * DM * DFF];

__device__ __forceinline__ void split1(float v, __nv_bfloat16& h, __nv_bfloat16& l) {
    h = __float2bfloat16(v);
    l = __float2bfloat16(v - __bfloat162float(h));
}
__device__ __forceinline__ void split4(const float* v, __nv_bfloat16* hp, __nv_bfloat16* lp) {
    __nv_bfloat16 h0, h1, h2, h3, l0, l1, l2, l3;
    split1(v[0], h0, l0); split1(v[1], h1, l1); split1(v[2], h2, l2); split1(v[3], h3, l3);
    __nv_bfloat162 hh0; hh0.x = h0; hh0.y = h1;
    __nv_bfloat162 hh1; hh1.x = h2; hh1.y = h3;
    __nv_bfloat162 ll0; ll0.x = l0; ll0.y = l1;
    __nv_bfloat162 ll1; ll1.x = l2; ll1.y = l3;
    *(__nv_bfloat162*)(hp)     = hh0;
    *(__nv_bfloat162*)(hp + 2) = hh1;
    *(__nv_bfloat162*)(lp)     = ll0;
    *(__nv_bfloat162*)(lp + 2) = ll1;
}

// ======================= fused weight split (one launch) =======================
__global__ void k_split_all(const float* __restrict__ Wqkv, const float* __restrict__ Wo,
                            const float* __restrict__ W1,   const float* __restrict__ W2,
                            __nv_bfloat16* wqh, __nv_bfloat16* wql,
                            __nv_bfloat16* woh, __nv_bfloat16* wol,
                            __nv_bfloat16* w1h, __nv_bfloat16* w1l,
                            __nv_bfloat16* w2h, __nv_bfloat16* w2l)
{
    const int N0 = NL * 3 * DM * DM / 4;
    const int N1 = NL * DM * DM / 4;
    const int N2 = NL * DFF * DM / 4;
    const int N3 = NL * DM * DFF / 4;
    int i = blockIdx.x * blockDim.x + threadIdx.x;
    const float* s; __nv_bfloat16 *h, *l; int j;
    if (i < N0)                { s = Wqkv; h = wqh; l = wql; j = i; }
    else if (i < N0+N1)        { s = Wo;   h = woh; l = wol; j = i - N0; }
    else if (i < N0+N1+N2)     { s = W1;   h = w1h; l = w1l; j = i - N0 - N1; }
    else if (i < N0+N1+N2+N3)  { s = W2;   h = w2h; l = w2l; j = i - N0 - N1 - N2; }
    else return;
    float v[4];
    *(float4*)v = *(const float4*)(s + (size_t)j * 4);
    split4(v, h + (size_t)j * 4, l + (size_t)j * 4);
}

// ======================= layout transposes =======================
__global__ void k_in(const float* __restrict__ x, float* __restrict__ xb,
                     __nv_bfloat16* __restrict__ xh, __nv_bfloat16* __restrict__ xl) {
    int idx = blockIdx.x * blockDim.x + threadIdx.x;
    if (idx >= MTOT * DM) return;
    int kcol = idx % DM;
    int row  = idx / DM;
    int b = row / SEQ, s = row % SEQ;
    float v = x[((size_t)(s * BATCH + b)) * DM + kcol];
    xb[idx] = v;
    __nv_bfloat16 h, l; split1(v, h, l);
    xh[idx] = h; xl[idx] = l;
}

__global__ void k_out(const float* __restrict__ xb, float* __restrict__ out) {
    int idx = blockIdx.x * blockDim.x + threadIdx.x;
    if (idx >= MTOT * DM) return;
    int kcol = idx % DM;
    int r    = idx / DM;
    int b = r % BATCH, s = r / BATCH;
    out[idx] = xb[((size_t)(b * SEQ + s)) * DM + kcol];
}

// ======================= HMMA GEMM (mma.sync bf16, 3-term split) =======================
#define PAD    72
#define TILE_B (128 * PAD * 2)
#define STGB   (4 * TILE_B)
#define TG_SMEM (2 * STGB)

template<int RELU, int SPLIT>
__global__ void __launch_bounds__(256, 1)
k_tgemm(const __nv_bfloat16* __restrict__ Ah, const __nv_bfloat16* __restrict__ Al,
        const __nv_bfloat16* __restrict__ Bh, const __nv_bfloat16* __restrict__ Bl,
        const float* __restrict__ bias,
        float* __restrict__ Cf, __nv_bfloat16* __restrict__ Ch, __nv_bfloat16* __restrict__ Cl,
        int M, int N, int K)
{
    extern __shared__ char dsm[];
    const uint32_t sbase = smem_to_u32(dsm);
    const int tid  = threadIdx.x;
    const int lane = tid & 31;
    const int wid  = tid >> 5;
    const int wm   = wid >> 2;
    const int wn   = wid & 3;
    const int m0 = blockIdx.y * 128;
    const int n0 = blockIdx.x * 128;
    const int nch = K >> 6;

    const __nv_bfloat16* srcs[4] = {Ah, Al, Bh, Bl};
    const int rowbase[4] = {m0, m0, n0, n0};

    float acc[4][4][4];
#pragma unroll
    for (int mt = 0; mt < 4; mt++)
#pragma unroll
        for (int nt = 0; nt < 4; nt++)
#pragma unroll
            for (int i = 0; i < 4; i++) acc[mt][nt][i] = 0.f;

    const uint32_t aoff = ((wm * 64 + (lane & 15)) * PAD + (lane >> 4) * 8) * 2;
    const uint32_t boff = ((wn * 32 + (lane & 7)) * PAD + ((lane >> 3) & 1) * 8) * 2;

#pragma unroll
    for (int i = 0; i < 16; i++) {
        int idx = tid + i * 256;
        int t = idx >> 10, r = (idx & 1023) >> 3, c = idx & 7;
        cpa16(sbase + t * TILE_B + r * (PAD * 2) + c * 16,
              srcs[t] + (size_t)(rowbase[t] + r) * K + c * 8);
    }
    asm volatile("cp.async.commit_group;" ::: "memory");

    const int tA[3] = {0, 0, 1};
    const int tB[3] = {2, 3, 2};

    for (int cch = 0; cch < nch; cch++) {
        if (cch + 1 < nch) {
            uint32_t stg = sbase + ((cch + 1) & 1) * STGB;
#pragma unroll
            for (int i = 0; i < 16; i++) {
                int idx = tid + i * 256;
                int t = idx >> 10, r = (idx & 1023) >> 3, c = idx & 7;
                cpa16(stg + t * TILE_B + r * (PAD * 2) + c * 16,
                      srcs[t] + (size_t)(rowbase[t] + r) * K + (cch + 1) * 64 + c * 8);
            }
        }
        asm volatile("cp.async.commit_group;" ::: "memory");
        asm volatile("cp.async.wait_group 1;" ::: "memory");
        __syncthreads();

        const uint32_t stg = sbase + (cch & 1) * STGB;
#pragma unroll
        for (int seg = 0; seg < 3; seg++) {
            const uint32_t Ab = stg + tA[seg] * TILE_B + aoff;
            const uint32_t Bb = stg + tB[seg] * TILE_B + boff;
#pragma unroll
            for (int ks = 0; ks < 4; ks++) {
                uint32_t a[4][4], b[4][2];
#pragma unroll
                for (int mt = 0; mt < 4; mt++)
                    ldsm_x4(a[mt], Ab + (mt * 16 * PAD + ks * 16) * 2);
#pragma unroll
                for (int nt = 0; nt < 4; nt++)
                    ldsm_x2(b[nt], Bb + (nt * 8 * PAD + ks * 16) * 2);
#pragma unroll
                for (int mt = 0; mt < 4; mt++)
#pragma unroll
                    for (int nt = 0; nt < 4; nt++)
                        mma16816(acc[mt][nt], a[mt], b[nt]);
            }
        }
        __syncthreads();
    }

    const int r0 = m0 + wm * 64 + (lane >> 2);
    const int c0 = n0 + wn * 32 + 2 * (lane & 3);
#pragma unroll
    for (int mt = 0; mt < 4; mt++) {
#pragma unroll
        for (int nt = 0; nt < 4; nt++) {
            int col = c0 + nt * 8;
            float b0 = bias[col], b1 = bias[col + 1];
#pragma unroll
            for (int half = 0; half < 2; half++) {
                int row = r0 + mt * 16 + half * 8;
                float v0 = acc[mt][nt][2 * half + 0] + b0;
                float v1 = acc[mt][nt][2 * half + 1] + b1;
                if (RELU) { v0 = fmaxf(v0, 0.f); v1 = fmaxf(v1, 0.f); }
                size_t off = (size_t)row * N + col;
                if (!SPLIT) {
                    float2 w = {v0, v1};
                    *(float2*)(Cf + off) = w;
                } else {
                    __nv_bfloat16 h0, l0, h1, l1;
                    split1(v0, h0, l0); split1(v1, h1, l1);
                    __nv_bfloat162 hh; hh.x = h0; hh.y = h1;
                    __nv_bfloat162 ll; ll.x = l0; ll.y = l1;
                    *(__nv_bfloat162*)(Ch + off) = hh;
                    *(__nv_bfloat162*)(Cl + off) = ll;
                }
            }
        }
    }
}

// ======================= banded attention v2 =======================
// 128-query tiles, 128 threads (1 query/thread), K/V double-buffered cp.async,
// probabilities in registers, float4-broadcast smem reads.
// smem: Qt [64][128] (32KB) + 2 stages x (K 16KB + V 16KB) = 96KB dynamic.
#define ATT_SMEM (32768 + 2 * 32768)

__global__ void __launch_bounds__(128)
k_attn(const float* __restrict__ qkv, __nv_bfloat16* __restrict__ ah, __nv_bfloat16* __restrict__ al)
{
    extern __shared__ float sm[];
    float (*Qt)[128] = (float(*)[128])sm;            // [64][128]: Qt[k][q]
    const uint32_t sbase = smem_to_u32(sm);
    const uint32_t stg_base = sbase + 32768;

    const int t = threadIdx.x;
    const int Qb = blockIdx.x, h = blockIdx.y, b = blockIdx.z;
    const int q  = Qb * 128 + t;
    const int nch = min(16, 2 * Qb + 3);
    const size_t rstr = 3 * DM;
    const float* base = qkv + (size_t)(b * SEQ) * rstr + h * HD;

    // load Q tile transposed (coalesced)
    {
        int rr0 = t >> 4;
        int c4 = (t & 15) * 4;
        for (int stp = 0; stp < 16; stp++) {
            int rr = stp * 8 + rr0;          // query row 0..127
            float4 v = *(const float4*)(base + (size_t)(Qb * 128 + rr) * rstr + c4);
            Qt[c4 + 0][rr] = v.x; Qt[c4 + 1][rr] = v.y;
            Qt[c4 + 2][rr] = v.z; Qt[c4 + 3][rr] = v.w;
        }
    }

    // prefetch chunk 0 -> stage 0 (K then V, 16 x 16B per thread)
    {
#pragma unroll
        for (int p = 0; p < 16; p++) {
            int lin = p * 128 + t;
            int which = lin >> 10, loc = lin & 1023;
            int row = loc >> 4, c4 = (loc & 15) * 4;
            cpa16(stg_base + which * 16384 + row * 256 + c4 * 4,
                  base + (size_t)(0 * 64 + row) * rstr + (which + 1) * DM + c4);
        }
        asm volatile("cp.async.commit_group;" ::: "memory");
    }

    float o[64];
#pragma unroll
    for (int d = 0; d < 64; d++) o[d] = 0.f;
    float mrow = -1e30f, lrow = 0.f;

    for (int c = 0; c < nch; c++) {
        asm volatile("cp.async.wait_group 0;" ::: "memory");
        __syncthreads();   // chunk c data visible; all warps done with chunk c-1

        // prefetch chunk c+1 into other stage (overlaps compute below)
        if (c + 1 < nch) {
            uint32_t stg = stg_base + ((c + 1) & 1) * 32768;
#pragma unroll
            for (int p = 0; p < 16; p++) {
                int lin = p * 128 + t;
                int which = lin >> 10, loc = lin & 1023;
                int row = loc >> 4, c4 = (loc & 15) * 4;
                cpa16(stg + which * 16384 + row * 256 + c4 * 4,
                      base + (size_t)((c + 1) * 64 + row) * rstr + (which + 1) * DM + c4);
            }
        }
        asm volatile("cp.async.commit_group;" ::: "memory");

        const float* Ks = sm + 8192 + (c & 1) * 8192;   // floats
        const float* Vs = Ks + 4096;

        // ---- scores s[j] = Q[q,:] . K[j,:] (4 k-quarters, float4 broadcast) ----
        float s[64];
#pragma unroll
        for (int j = 0; j < 64; j++) s[j] = 0.f;
#pragma unroll
        for (int qu = 0; qu < 4; qu++) {
            float qreg[16];
#pragma unroll
            for (int kk = 0; kk < 16; kk++) qreg[kk] = Qt[qu * 16 + kk][t];
#pragma unroll 8
            for (int j = 0; j < 64; j++) {
                const float4* kr = (const float4*)(Ks + j * 64 + qu * 16);
                float a0 = 0.f, a1 = 0.f;
#pragma unroll
                for (int k4 = 0; k4 < 4; k4 += 2) {
                    float4 kv0 = kr[k4], kv1 = kr[k4 + 1];
                    a0 += qreg[k4*4+0]*kv0.x + qreg[k4*4+1]*kv0.y + qreg[k4*4+2]*kv0.z + qreg[k4*4+3]*kv0.w;
                    a1 += qreg[k4*4+4]*kv1.x + qreg[k4*4+5]*kv1.y + qreg[k4*4+6]*kv1.z + qreg[k4*4+7]*kv1.w;
                }
                s[j] += a0 + a1;
            }
        }

        // ---- mask + online softmax ----
        const float scale = 0.125f;
        float mc = -1e30f;
        if (c >= 2 * Qb + 1) {
            int lim = q + WIN - c * 64;     // j <= lim allowed
#pragma unroll
            for (int j = 0; j < 64; j++) {
                float sv = (j <= lim) ? s[j] * scale : -1e30f;
                s[j] = sv;
                mc = fmaxf(mc, sv);
            }
        } else {
#pragma unroll
            for (int j = 0; j < 64; j++) {
                float sv = s[j] * scale;
                s[j] = sv;
                mc = fmaxf(mc, sv);
            }
        }
        float mnew  = fmaxf(mrow, mc);
        float alpha = __expf(mrow - mnew);
        lrow *= alpha;
#pragma unroll
        for (int d = 0; d < 64; d++) o[d] *= alpha;
#pragma unroll
        for (int j = 0; j < 64; j++) {
            float p = __expf(s[j] - mnew);
            s[j] = p;
            lrow += p;
        }
        mrow = mnew;

        // ---- o += P . V (float4 broadcast) ----
#pragma unroll 8
        for (int j = 0; j < 64; j++) {
            float p = s[j];
            const float4* vr = (const float4*)(Vs + j * 64);
#pragma unroll
            for (int d4 = 0; d4 < 16; d4++) {
                float4 v = vr[d4];
                o[d4*4+0] += p * v.x; o[d4*4+1] += p * v.y;
                o[d4*4+2] += p * v.z; o[d4*4+3] += p * v.w;
            }
        }
    }

    float inv = 1.0f / lrow;
    size_t off = (size_t)(b * SEQ + q) * DM + h * HD;
#pragma unroll
    for (int d = 0; d < 64; d += 4) {
        float v[4] = {o[d] * inv, o[d+1] * inv, o[d+2] * inv, o[d+3] * inv};
        split4(v, ah + off + d, al + off + d);
    }
}

// ======================= LayerNorm(resid + delta) -> fp32 + hi/lo =======================
__global__ void __launch_bounds__(256)
k_ln(const float* __restrict__ resid, const float* __restrict__ delta,
     const float* __restrict__ gamma, const float* __restrict__ beta,
     float* __restrict__ out, __nv_bfloat16* __restrict__ oh, __nv_bfloat16* __restrict__ ol)
{
    __shared__ float red[8];
    const int row = blockIdx.x;
    const int t = threadIdx.x;
    const float* rp = resid + (size_t)row * DM;
    const float* dp = delta + (size_t)row * DM;

    float4 rv = *(const float4*)(rp + t * 4);
    float4 dv = *(const float4*)(dp + t * 4);
    float v[4] = {rv.x + dv.x, rv.y + dv.y, rv.z + dv.z, rv.w + dv.w};

    float s = v[0] + v[1] + v[2] + v[3];
#pragma unroll
    for (int off = 16; off; off >>= 1) s += __shfl_xor_sync(~0u, s, off);
    if ((t & 31) == 0) red[t >> 5] = s;
    __syncthreads();
    if (t < 8) {
        float x = red[t];
#pragma unroll
        for (int off = 4; off; off >>= 1) x += __shfl_xor_sync(0xffu, x, off);
        if (t == 0) red[0] = x;
    }
    __syncthreads();
    float mu = red[0] * (1.0f / DM);
    __syncthreads();

    float vs = 0.f;
#pragma unroll
    for (int i = 0; i < 4; i++) { float d = v[i] - mu; vs += d * d; }
#pragma unroll
    for (int off = 16; off; off >>= 1) vs += __shfl_xor_sync(~0u, vs, off);
    if ((t & 31) == 0) red[t >> 5] = vs;
    __syncthreads();
    if (t < 8) {
        float x = red[t];
#pragma unroll
        for (int off = 4; off; off >>= 1) x += __shfl_xor_sync(0xffu, x, off);
        if (t == 0) red[0] = x;
    }
    __syncthreads();
    float rstd = rsqrtf(red[0] * (1.0f / DM) + 1e-5f);

    float4 g4 = *(const float4*)(gamma + t * 4);
    float4 b4 = *(const float4*)(beta  + t * 4);
    float w[4];
    w[0] = (v[0] - mu) * rstd * g4.x + b4.x;
    w[1] = (v[1] - mu) * rstd * g4.y + b4.y;
    w[2] = (v[2] - mu) * rstd * g4.z + b4.z;
    w[3] = (v[3] - mu) * rstd * g4.w + b4.w;
    float4 wf = {w[0], w[1], w[2], w[3]};
    *(float4*)(out + (size_t)row * DM + t * 4) = wf;
    split4(w, oh + (size_t)row * DM + t * 4, ol + (size_t)row * DM + t * 4);
}

// ======================= host driver =======================
extern "C" void kernel_launch(void* const* d_in, const int* in_sizes, int n_in,
                              void* d_out, int out_size)
{
    const float* x    = (const float*)d_in[0];
    const float* Wqkv = (const float*)d_in[1];
    const float* bqkv = (const float*)d_in[2];
    const float* Wo   = (const float*)d_in[3];
    const float* bo   = (const float*)d_in[4];
    const float* W1   = (const float*)d_in[5];
    const float* b1   = (const float*)d_in[6];
    const float* W2   = (const float*)d_in[7];
    const float* b2   = (const float*)d_in[8];
    const float* g1   = (const float*)d_in[9];
    const float* be1  = (const float*)d_in[10];
    const float* g2   = (const float*)d_in[11];
    const float* be2  = (const float*)d_in[12];
    float* out = (float*)d_out;

    float *p_xb, *p_qkv, *p_delta;
    __nv_bfloat16 *p_xh, *p_xl, *p_ah, *p_al, *p_fh, *p_fl;
    __nv_bfloat16 *p_wqh, *p_wql, *p_woh, *p_wol, *p_w1h, *p_w1l, *p_w2h, *p_w2l;
    cudaGetSymbolAddress((void**)&p_xb,  g_xb);
    cudaGetSymbolAddress((void**)&p_qkv, g_qkv);
    cudaGetSymbolAddress((void**)&p_delta, g_delta);
    cudaGetSymbolAddress((void**)&p_xh,  g_xh);
    cudaGetSymbolAddress((void**)&p_xl,  g_xl);
    cudaGetSymbolAddress((void**)&p_ah,  g_ah);
    cudaGetSymbolAddress((void**)&p_al,  g_al);
    cudaGetSymbolAddress((void**)&p_fh,  g_fh);
    cudaGetSymbolAddress((void**)&p_fl,  g_fl);
    cudaGetSymbolAddress((void**)&p_wqh, g_wqh);
    cudaGetSymbolAddress((void**)&p_wql, g_wql);
    cudaGetSymbolAddress((void**)&p_woh, g_woh);
    cudaGetSymbolAddress((void**)&p_wol, g_wol);
    cudaGetSymbolAddress((void**)&p_w1h, g_w1h);
    cudaGetSymbolAddress((void**)&p_w1l, g_w1l);
    cudaGetSymbolAddress((void**)&p_w2h, g_w2h);
    cudaGetSymbolAddress((void**)&p_w2l, g_w2l);

    cudaFuncSetAttribute(k_tgemm<0,0>, cudaFuncAttributeMaxDynamicSharedMemorySize, TG_SMEM);
    cudaFuncSetAttribute(k_tgemm<1,1>, cudaFuncAttributeMaxDynamicSharedMemorySize, TG_SMEM);
    cudaFuncSetAttribute(k_attn, cudaFuncAttributeMaxDynamicSharedMemorySize, ATT_SMEM);

    // one fused weight-split launch
    {
        int ntot = (NL * 3 * DM * DM + NL * DM * DM + NL * DFF * DM + NL * DM * DFF) / 4;
        k_split_all<<<(ntot + 255) / 256, 256>>>(Wqkv, Wo, W1, W2,
            p_wqh, p_wql, p_woh, p_wol, p_w1h, p_w1l, p_w2h, p_w2l);
    }

    const int nElem = MTOT * DM;
    k_in<<<(nElem + 255) / 256, 256>>>(x, p_xb, p_xh, p_xl);

    for (int l = 0; l < NL; l++) {
        k_tgemm<0,0><<<dim3(3 * DM / 128, MTOT / 128), 256, TG_SMEM>>>(
            p_xh, p_xl,
            p_wqh + (size_t)l * 3 * DM * DM, p_wql + (size_t)l * 3 * DM * DM,
            bqkv + (size_t)l * 3 * DM,
            p_qkv, nullptr, nullptr, MTOT, 3 * DM, DM);

        k_attn<<<dim3(SEQ / 128, NH, BATCH), 128, ATT_SMEM>>>(p_qkv, p_ah, p_al);

        k_tgemm<0,0><<<dim3(DM / 128, MTOT / 128), 256, TG_SMEM>>>(
            p_ah, p_al,
            p_woh + (size_t)l * DM * DM, p_wol + (size_t)l * DM * DM,
            bo + (size_t)l * DM,
            p_delta, nullptr, nullptr, MTOT, DM, DM);

        k_ln<<<MTOT, 256>>>(p_xb, p_delta, g1 + (size_t)l * DM, be1 + (size_t)l * DM,
                            p_xb, p_xh, p_xl);

        k_tgemm<1,1><<<dim3(DFF / 128, MTOT / 128), 256, TG_SMEM>>>(
            p_xh, p_xl,
            p_w1h + (size_t)l * DFF * DM, p_w1l + (size_t)l * DFF * DM,
            b1 + (size_t)l * DFF,
            nullptr, p_fh, p_fl, MTOT, DFF, DM);

        k_tgemm<0,0><<<dim3(DM / 128, MTOT / 128), 256, TG_SMEM>>>(
            p_fh, p_fl,
            p_w2h + (size_t)l * DM * DFF, p_w2l + (size_t)l * DM * DFF,
            b2 + (size_t)l * DM,
            p_delta, nullptr, nullptr, MTOT, DM, DFF);

        k_ln<<<MTOT, 256>>>(p_xb, p_delta, g2 + (size_t)l * DM, be2 + (size_t)l * DM,
                            p_xb, p_xh, p_xl);
    }

    k_out<<<(nElem + 255) / 256, 256>>>(p_xb, out);
}

// round 7
// speedup vs baseline: 2.7404x; 1.4216x over previous
#include <cuda_runtime.h>
#include <cuda_bf16.h>
#include <cstdint>

#define SEQ   1024
#define BATCH 4
#define DM    1024
#define NH    16
#define HD    64
#define DFF   4096
#define NL    4
#define WIN   64
#define MTOT  (SEQ*BATCH)

// ======================= PTX helpers (sm_80+ features only) =======================
__device__ __forceinline__ uint32_t smem_to_u32(const void* p) {
    uint32_t a;
    asm("{ .reg .u64 t; cvta.to.shared.u64 t, %1; cvt.u32.u64 %0, t; }" : "=r"(a) : "l"(p));
    return a;
}
__device__ __forceinline__ void cpa16(uint32_t smem, const void* gmem) {
    asm volatile("cp.async.cg.shared.global [%0], [%1], 16;" :: "r"(smem), "l"(gmem) : "memory");
}
__device__ __forceinline__ void ldsm_x4(uint32_t* r, uint32_t addr) {
    asm volatile("ldmatrix.sync.aligned.m8n8.x4.shared.b16 {%0,%1,%2,%3}, [%4];"
        : "=r"(r[0]), "=r"(r[1]), "=r"(r[2]), "=r"(r[3]) : "r"(addr));
}
__device__ __forceinline__ void ldsm_x2(uint32_t* r, uint32_t addr) {
    asm volatile("ldmatrix.sync.aligned.m8n8.x2.shared.b16 {%0,%1}, [%2];"
        : "=r"(r[0]), "=r"(r[1]) : "r"(addr));
}
__device__ __forceinline__ void ldsm_x2t(uint32_t* r, uint32_t addr) {
    asm volatile("ldmatrix.sync.aligned.m8n8.x2.trans.shared.b16 {%0,%1}, [%2];"
        : "=r"(r[0]), "=r"(r[1]) : "r"(addr));
}
__device__ __forceinline__ void mma16816(float* c, const uint32_t* a, const uint32_t* b) {
    asm volatile(
        "mma.sync.aligned.m16n8k16.row.col.f32.bf16.bf16.f32 "
        "{%0,%1,%2,%3}, {%4,%5,%6,%7}, {%8,%9}, {%0,%1,%2,%3};"
        : "+f"(c[0]), "+f"(c[1]), "+f"(c[2]), "+f"(c[3])
        : "r"(a[0]), "r"(a[1]), "r"(a[2]), "r"(a[3]), "r"(b[0]), "r"(b[1]));
}

// ======================= scratch (device globals) =======================
__device__ __align__(256) float          g_xb   [MTOT * DM];
__device__ __align__(256) __nv_bfloat16  g_xh   [MTOT * DM];
__device__ __align__(256) __nv_bfloat16  g_xl   [MTOT * DM];
__device__ __align__(256) __nv_bfloat16  g_qkvh [MTOT * 3 * DM];
__device__ __align__(256) __nv_bfloat16  g_qkvl [MTOT * 3 * DM];
__device__ __align__(256) __nv_bfloat16  g_ah   [MTOT * DM];
__device__ __align__(256) __nv_bfloat16  g_al   [MTOT * DM];
__device__ __align__(256) float          g_delta[MTOT * DM];
__device__ __align__(256) __nv_bfloat16  g_fh   [MTOT * DFF];
__device__ __align__(256) __nv_bfloat16  g_fl   [MTOT * DFF];
__device__ __align__(256) __nv_bfloat16  g_wqh  [NL * 3 * DM * DM];
__device__ __align__(256) __nv_bfloat16  g_wql  [NL * 3 * DM * DM];
__device__ __align__(256) __nv_bfloat16  g_woh  [NL * DM * DM];
__device__ __align__(256) __nv_bfloat16  g_wol  [NL * DM * DM];
__device__ __align__(256) __nv_bfloat16  g_w1h  [NL * DFF * DM];
__device__ __align__(256) __nv_bfloat16  g_w1l  [NL * DFF * DM];
__device__ __align__(256) __nv_bfloat16  g_w2h  [NL * DM * DFF];
__device__ __align__(256) __nv_bfloat16  g_w2l  [NL * DM * DFF];

__device__ __forceinline__ void split1(float v, __nv_bfloat16& h, __nv_bfloat16& l) {
    h = __float2bfloat16(v);
    l = __float2bfloat16(v - __bfloat162float(h));
}
__device__ __forceinline__ void split4(const float* v, __nv_bfloat16* hp, __nv_bfloat16* lp) {
    __nv_bfloat16 h0, h1, h2, h3, l0, l1, l2, l3;
    split1(v[0], h0, l0); split1(v[1], h1, l1); split1(v[2], h2, l2); split1(v[3], h3, l3);
    __nv_bfloat162 hh0; hh0.x = h0; hh0.y = h1;
    __nv_bfloat162 hh1; hh1.x = h2; hh1.y = h3;
    __nv_bfloat162 ll0; ll0.x = l0; ll0.y = l1;
    __nv_bfloat162 ll1; ll1.x = l2; ll1.y = l3;
    *(__nv_bfloat162*)(hp)     = hh0;
    *(__nv_bfloat162*)(hp + 2) = hh1;
    *(__nv_bfloat162*)(lp)     = ll0;
    *(__nv_bfloat162*)(lp + 2) = ll1;
}
// pack two floats into bf16x2 hi-part and lo-part (low element first)
__device__ __forceinline__ void psplit2(float p0, float p1, uint32_t& hi, uint32_t& lo) {
    __nv_bfloat16 h0 = __float2bfloat16(p0), h1 = __float2bfloat16(p1);
    __nv_bfloat16 r0 = __float2bfloat16(p0 - __bfloat162float(h0));
    __nv_bfloat16 r1 = __float2bfloat16(p1 - __bfloat162float(h1));
    __nv_bfloat162 H; H.x = h0; H.y = h1;
    __nv_bfloat162 L; L.x = r0; L.y = r1;
    hi = *(uint32_t*)&H; lo = *(uint32_t*)&L;
}

// ======================= fused weight split =======================
__global__ void k_split_all(const float* __restrict__ Wqkv, const float* __restrict__ Wo,
                            const float* __restrict__ W1,   const float* __restrict__ W2,
                            __nv_bfloat16* wqh, __nv_bfloat16* wql,
                            __nv_bfloat16* woh, __nv_bfloat16* wol,
                            __nv_bfloat16* w1h, __nv_bfloat16* w1l,
                            __nv_bfloat16* w2h, __nv_bfloat16* w2l)
{
    const int N0 = NL * 3 * DM * DM / 4;
    const int N1 = NL * DM * DM / 4;
    const int N2 = NL * DFF * DM / 4;
    const int N3 = NL * DM * DFF / 4;
    int i = blockIdx.x * blockDim.x + threadIdx.x;
    const float* s; __nv_bfloat16 *h, *l; int j;
    if (i < N0)                { s = Wqkv; h = wqh; l = wql; j = i; }
    else if (i < N0+N1)        { s = Wo;   h = woh; l = wol; j = i - N0; }
    else if (i < N0+N1+N2)     { s = W1;   h = w1h; l = w1l; j = i - N0 - N1; }
    else if (i < N0+N1+N2+N3)  { s = W2;   h = w2h; l = w2l; j = i - N0 - N1 - N2; }
    else return;
    float v[4];
    *(float4*)v = *(const float4*)(s + (size_t)j * 4);
    split4(v, h + (size_t)j * 4, l + (size_t)j * 4);
}

// ======================= layout transposes =======================
__global__ void k_in(const float* __restrict__ x, float* __restrict__ xb,
                     __nv_bfloat16* __restrict__ xh, __nv_bfloat16* __restrict__ xl) {
    int idx = blockIdx.x * blockDim.x + threadIdx.x;
    if (idx >= MTOT * DM) return;
    int kcol = idx % DM;
    int row  = idx / DM;
    int b = row / SEQ, s = row % SEQ;
    float v = x[((size_t)(s * BATCH + b)) * DM + kcol];
    xb[idx] = v;
    __nv_bfloat16 h, l; split1(v, h, l);
    xh[idx] = h; xl[idx] = l;
}

__global__ void k_out(const float* __restrict__ xb, float* __restrict__ out) {
    int idx = blockIdx.x * blockDim.x + threadIdx.x;
    if (idx >= MTOT * DM) return;
    int kcol = idx % DM;
    int r    = idx / DM;
    int b = r % BATCH, s = r / BATCH;
    out[idx] = xb[((size_t)(b * SEQ + s)) * DM + kcol];
}

// ======================= HMMA GEMM (mma.sync bf16, 3-term split) =======================
#define PAD    72
#define TILE_B (128 * PAD * 2)
#define STGB   (4 * TILE_B)
#define TG_SMEM (2 * STGB)

template<int RELU, int SPLIT>
__global__ void __launch_bounds__(256, 1)
k_tgemm(const __nv_bfloat16* __restrict__ Ah, const __nv_bfloat16* __restrict__ Al,
        const __nv_bfloat16* __restrict__ Bh, const __nv_bfloat16* __restrict__ Bl,
        const float* __restrict__ bias,
        float* __restrict__ Cf, __nv_bfloat16* __restrict__ Ch, __nv_bfloat16* __restrict__ Cl,
        int M, int N, int K)
{
    extern __shared__ char dsm[];
    const uint32_t sbase = smem_to_u32(dsm);
    const int tid  = threadIdx.x;
    const int lane = tid & 31;
    const int wid  = tid >> 5;
    const int wm   = wid >> 2;
    const int wn   = wid & 3;
    const int m0 = blockIdx.y * 128;
    const int n0 = blockIdx.x * 128;
    const int nch = K >> 6;

    const __nv_bfloat16* srcs[4] = {Ah, Al, Bh, Bl};
    const int rowbase[4] = {m0, m0, n0, n0};

    float acc[4][4][4];
#pragma unroll
    for (int mt = 0; mt < 4; mt++)
#pragma unroll
        for (int nt = 0; nt < 4; nt++)
#pragma unroll
            for (int i = 0; i < 4; i++) acc[mt][nt][i] = 0.f;

    const uint32_t aoff = ((wm * 64 + (lane & 15)) * PAD + (lane >> 4) * 8) * 2;
    const uint32_t boff = ((wn * 32 + (lane & 7)) * PAD + ((lane >> 3) & 1) * 8) * 2;

#pragma unroll
    for (int i = 0; i < 16; i++) {
        int idx = tid + i * 256;
        int t = idx >> 10, r = (idx & 1023) >> 3, c = idx & 7;
        cpa16(sbase + t * TILE_B + r * (PAD * 2) + c * 16,
              srcs[t] + (size_t)(rowbase[t] + r) * K + c * 8);
    }
    asm volatile("cp.async.commit_group;" ::: "memory");

    const int tA[3] = {0, 0, 1};
    const int tB[3] = {2, 3, 2};

    for (int cch = 0; cch < nch; cch++) {
        if (cch + 1 < nch) {
            uint32_t stg = sbase + ((cch + 1) & 1) * STGB;
#pragma unroll
            for (int i = 0; i < 16; i++) {
                int idx = tid + i * 256;
                int t = idx >> 10, r = (idx & 1023) >> 3, c = idx & 7;
                cpa16(stg + t * TILE_B + r * (PAD * 2) + c * 16,
                      srcs[t] + (size_t)(rowbase[t] + r) * K + (cch + 1) * 64 + c * 8);
            }
        }
        asm volatile("cp.async.commit_group;" ::: "memory");
        asm volatile("cp.async.wait_group 1;" ::: "memory");
        __syncthreads();

        const uint32_t stg = sbase + (cch & 1) * STGB;
#pragma unroll
        for (int seg = 0; seg < 3; seg++) {
            const uint32_t Ab = stg + tA[seg] * TILE_B + aoff;
            const uint32_t Bb = stg + tB[seg] * TILE_B + boff;
#pragma unroll
            for (int ks = 0; ks < 4; ks++) {
                uint32_t a[4][4], b[4][2];
#pragma unroll
                for (int mt = 0; mt < 4; mt++)
                    ldsm_x4(a[mt], Ab + (mt * 16 * PAD + ks * 16) * 2);
#pragma unroll
                for (int nt = 0; nt < 4; nt++)
                    ldsm_x2(b[nt], Bb + (nt * 8 * PAD + ks * 16) * 2);
#pragma unroll
                for (int mt = 0; mt < 4; mt++)
#pragma unroll
                    for (int nt = 0; nt < 4; nt++)
                        mma16816(acc[mt][nt], a[mt], b[nt]);
            }
        }
        __syncthreads();
    }

    const int r0 = m0 + wm * 64 + (lane >> 2);
    const int c0 = n0 + wn * 32 + 2 * (lane & 3);
#pragma unroll
    for (int mt = 0; mt < 4; mt++) {
#pragma unroll
        for (int nt = 0; nt < 4; nt++) {
            int col = c0 + nt * 8;
            float b0 = bias[col], b1 = bias[col + 1];
#pragma unroll
            for (int half = 0; half < 2; half++) {
                int row = r0 + mt * 16 + half * 8;
                float v0 = acc[mt][nt][2 * half + 0] + b0;
                float v1 = acc[mt][nt][2 * half + 1] + b1;
                if (RELU) { v0 = fmaxf(v0, 0.f); v1 = fmaxf(v1, 0.f); }
                size_t off = (size_t)row * N + col;
                if (!SPLIT) {
                    float2 w = {v0, v1};
                    *(float2*)(Cf + off) = w;
                } else {
                    __nv_bfloat16 h0, l0, h1, l1;
                    split1(v0, h0, l0); split1(v1, h1, l1);
                    __nv_bfloat162 hh; hh.x = h0; hh.y = h1;
                    __nv_bfloat162 ll; ll.x = l0; ll.y = l1;
                    *(__nv_bfloat162*)(Ch + off) = hh;
                    *(__nv_bfloat162*)(Cl + off) = ll;
                }
            }
        }
    }
}

// ======================= HMMA banded flash attention =======================
// 128 queries/block, 8 warps (warp w = rows w*16..w*16+15), 64-key chunks.
// S = Qh.Kh + Qh.Kl + Ql.Kh; O += Ph.Vh + Ph.Vl + Pl.Vh.
// smem: Qh,Ql 128x72 bf16 + 2 stages x (Kh,Kl,Vh,Vl 64x72 bf16).
#define AP     72
#define AROWB  (AP * 2)          // 144 bytes per padded row
#define QTILEB (128 * AROWB)     // 18432
#define ATILEB (64 * AROWB)      // 9216
#define ASTGB  (4 * ATILEB)      // 36864
#define ATT_SMEM (2 * QTILEB + 2 * ASTGB)   // 110592

__global__ void __launch_bounds__(256, 1)
k_attn(const __nv_bfloat16* __restrict__ qh, const __nv_bfloat16* __restrict__ ql,
       __nv_bfloat16* __restrict__ ah, __nv_bfloat16* __restrict__ al)
{
    extern __shared__ char asm_[];
    const uint32_t sbase = smem_to_u32(asm_);
    const uint32_t Qh_s = sbase, Ql_s = sbase + QTILEB;
    const uint32_t stg0 = sbase + 2 * QTILEB;

    const int tid = threadIdx.x;
    const int lane = tid & 31;
    const int w = tid >> 5;
    const int Qb = blockIdx.x, h = blockIdx.y, b = blockIdx.z;
    const int nch = min(16, 2 * Qb + 3);
    const size_t rstr = 3 * DM;
    const size_t rowoff0 = (size_t)(b * SEQ) * rstr + h * HD;

    // ---- load Q tiles (hi/lo) via cp.async ----
#pragma unroll
    for (int i = 0; i < 8; i++) {
        int lin = i * 256 + tid;
        int hl = lin >> 10, loc = lin & 1023;
        int r = loc >> 3, p = loc & 7;
        const __nv_bfloat16* src = (hl ? ql : qh) + rowoff0 + (size_t)(Qb * 128 + r) * rstr + p * 8;
        cpa16((hl ? Ql_s : Qh_s) + r * AROWB + p * 16, src);
    }
    // ---- chunk 0 K/V ----
#pragma unroll
    for (int i = 0; i < 8; i++) {
        int lin = i * 256 + tid;
        int t = lin >> 9, loc = lin & 511;
        int r = loc >> 3, p = loc & 7;
        const __nv_bfloat16* src = ((t & 1) ? ql : qh) + rowoff0
            + (size_t)(0 + r) * rstr + ((t < 2) ? DM : 2 * DM) + p * 8;
        cpa16(stg0 + t * ATILEB + r * AROWB + p * 16, src);
    }
    asm volatile("cp.async.commit_group;" ::: "memory");
    asm volatile("cp.async.wait_group 0;" ::: "memory");
    __syncthreads();

    // ---- Q fragments (held in registers for the whole kernel) ----
    uint32_t qfh[4][4], qfl[4][4];
    {
        uint32_t qaddr = ((w * 16 + (lane & 15)) * AROWB) + (lane >> 4) * 16;
#pragma unroll
        for (int ks = 0; ks < 4; ks++) {
            ldsm_x4(qfh[ks], Qh_s + qaddr + ks * 32);
            ldsm_x4(qfl[ks], Ql_s + qaddr + ks * 32);
        }
    }

    float oacc[8][4];
#pragma unroll
    for (int nt = 0; nt < 8; nt++)
#pragma unroll
        for (int i = 0; i < 4; i++) oacc[nt][i] = 0.f;
    float m0 = -1e30f, m1 = -1e30f, l0 = 0.f, l1 = 0.f;

    const int q0 = Qb * 128 + w * 16 + (lane >> 2);
    const int lim0 = q0 + WIN, lim1 = q0 + 8 + WIN;
    const uint32_t kfoff = ((lane & 7) * AROWB) + ((lane >> 3) & 1) * 16;
    const uint32_t vfoff = ((lane & 15) * AROWB);

    for (int c = 0; c < nch; c++) {
        if (c > 0) {
            asm volatile("cp.async.wait_group 0;" ::: "memory");
            __syncthreads();
        }
        // prefetch next chunk
        if (c + 1 < nch) {
            uint32_t stg = stg0 + ((c + 1) & 1) * ASTGB;
#pragma unroll
            for (int i = 0; i < 8; i++) {
                int lin = i * 256 + tid;
                int t = lin >> 9, loc = lin & 511;
                int r = loc >> 3, p = loc & 7;
                const __nv_bfloat16* src = ((t & 1) ? ql : qh) + rowoff0
                    + (size_t)((c + 1) * 64 + r) * rstr + ((t < 2) ? DM : 2 * DM) + p * 8;
                cpa16(stg + t * ATILEB + r * AROWB + p * 16, src);
            }
        }
        asm volatile("cp.async.commit_group;" ::: "memory");

        const uint32_t stg = stg0 + (c & 1) * ASTGB;
        const uint32_t Kh_s = stg, Kl_s = stg + ATILEB;
        const uint32_t Vh_s = stg + 2 * ATILEB, Vl_s = stg + 3 * ATILEB;

        // ---- S = Q . K^T ----
        float sacc[8][4];
#pragma unroll
        for (int nt = 0; nt < 8; nt++)
#pragma unroll
            for (int i = 0; i < 4; i++) sacc[nt][i] = 0.f;
#pragma unroll
        for (int ks = 0; ks < 4; ks++) {
#pragma unroll
            for (int nt = 0; nt < 8; nt++) {
                uint32_t kh[2], kl[2];
                uint32_t off = nt * 8 * AROWB + kfoff + ks * 32;
                ldsm_x2(kh, Kh_s + off);
                ldsm_x2(kl, Kl_s + off);
                mma16816(sacc[nt], qfh[ks], kh);
                mma16816(sacc[nt], qfh[ks], kl);
                mma16816(sacc[nt], qfl[ks], kh);
            }
        }

        // ---- mask + online softmax on fragments ----
        const float scale = 0.125f;
        float mc0 = -1e30f, mc1 = -1e30f;
        const bool domask = (c >= 2 * Qb + 1);
        const int jb = c * 64 + 2 * (lane & 3);
#pragma unroll
        for (int nt = 0; nt < 8; nt++) {
            int j0 = jb + nt * 8, j1 = j0 + 1;
            float s0 = sacc[nt][0] * scale, s1 = sacc[nt][1] * scale;
            float s2 = sacc[nt][2] * scale, s3 = sacc[nt][3] * scale;
            if (domask) {
                if (j0 > lim0) s0 = -1e30f;
                if (j1 > lim0) s1 = -1e30f;
                if (j0 > lim1) s2 = -1e30f;
                if (j1 > lim1) s3 = -1e30f;
            }
            sacc[nt][0] = s0; sacc[nt][1] = s1; sacc[nt][2] = s2; sacc[nt][3] = s3;
            mc0 = fmaxf(mc0, fmaxf(s0, s1));
            mc1 = fmaxf(mc1, fmaxf(s2, s3));
        }
        mc0 = fmaxf(mc0, __shfl_xor_sync(~0u, mc0, 1));
        mc0 = fmaxf(mc0, __shfl_xor_sync(~0u, mc0, 2));
        mc1 = fmaxf(mc1, __shfl_xor_sync(~0u, mc1, 1));
        mc1 = fmaxf(mc1, __shfl_xor_sync(~0u, mc1, 2));
        float m0n = fmaxf(m0, mc0), m1n = fmaxf(m1, mc1);
        float a0 = __expf(m0 - m0n), a1 = __expf(m1 - m1n);
        l0 *= a0; l1 *= a1;
#pragma unroll
        for (int nt = 0; nt < 8; nt++) {
            oacc[nt][0] *= a0; oacc[nt][1] *= a0;
            oacc[nt][2] *= a1; oacc[nt][3] *= a1;
        }
#pragma unroll
        for (int nt = 0; nt < 8; nt++) {
            float p0 = __expf(sacc[nt][0] - m0n), p1 = __expf(sacc[nt][1] - m0n);
            float p2 = __expf(sacc[nt][2] - m1n), p3 = __expf(sacc[nt][3] - m1n);
            sacc[nt][0] = p0; sacc[nt][1] = p1; sacc[nt][2] = p2; sacc[nt][3] = p3;
            l0 += p0 + p1; l1 += p2 + p3;
        }
        m0 = m0n; m1 = m1n;

        // ---- O += P . V ----
#pragma unroll
        for (int kk = 0; kk < 4; kk++) {
            uint32_t pah[4], pal[4];
            psplit2(sacc[2*kk][0],   sacc[2*kk][1],   pah[0], pal[0]);
            psplit2(sacc[2*kk][2],   sacc[2*kk][3],   pah[1], pal[1]);
            psplit2(sacc[2*kk+1][0], sacc[2*kk+1][1], pah[2], pal[2]);
            psplit2(sacc[2*kk+1][2], sacc[2*kk+1][3], pah[3], pal[3]);
#pragma unroll
            for (int nt = 0; nt < 8; nt++) {
                uint32_t vh[2], vl[2];
                uint32_t off = kk * 16 * AROWB + vfoff + nt * 16;
                ldsm_x2t(vh, Vh_s + off);
                ldsm_x2t(vl, Vl_s + off);
                mma16816(oacc[nt], pah, vh);
                mma16816(oacc[nt], pah, vl);
                mma16816(oacc[nt], pal, vh);
            }
        }
    }

    // ---- finalize: row sums across quad, scale, write bf16 hi/lo ----
    l0 += __shfl_xor_sync(~0u, l0, 1); l0 += __shfl_xor_sync(~0u, l0, 2);
    l1 += __shfl_xor_sync(~0u, l1, 1); l1 += __shfl_xor_sync(~0u, l1, 2);
    float inv0 = 1.0f / l0, inv1 = 1.0f / l1;
    size_t orow0 = (size_t)(b * SEQ + q0) * DM + h * HD;
    size_t orow1 = orow0 + (size_t)8 * DM;
    int cbase = 2 * (lane & 3);
#pragma unroll
    for (int nt = 0; nt < 8; nt++) {
        int col = cbase + nt * 8;
        uint32_t hi, lo;
        psplit2(oacc[nt][0] * inv0, oacc[nt][1] * inv0, hi, lo);
        *(uint32_t*)(ah + orow0 + col) = hi;
        *(uint32_t*)(al + orow0 + col) = lo;
        psplit2(oacc[nt][2] * inv1, oacc[nt][3] * inv1, hi, lo);
        *(uint32_t*)(ah + orow1 + col) = hi;
        *(uint32_t*)(al + orow1 + col) = lo;
    }
}

// ======================= LayerNorm(resid + delta) -> fp32 + hi/lo =======================
__global__ void __launch_bounds__(256)
k_ln(const float* __restrict__ resid, const float* __restrict__ delta,
     const float* __restrict__ gamma, const float* __restrict__ beta,
     float* __restrict__ out, __nv_bfloat16* __restrict__ oh, __nv_bfloat16* __restrict__ ol)
{
    __shared__ float red[8];
    const int row = blockIdx.x;
    const int t = threadIdx.x;
    const float* rp = resid + (size_t)row * DM;
    const float* dp = delta + (size_t)row * DM;

    float4 rv = *(const float4*)(rp + t * 4);
    float4 dv = *(const float4*)(dp + t * 4);
    float v[4] = {rv.x + dv.x, rv.y + dv.y, rv.z + dv.z, rv.w + dv.w};

    float s = v[0] + v[1] + v[2] + v[3];
#pragma unroll
    for (int off = 16; off; off >>= 1) s += __shfl_xor_sync(~0u, s, off);
    if ((t & 31) == 0) red[t >> 5] = s;
    __syncthreads();
    if (t < 8) {
        float x = red[t];
#pragma unroll
        for (int off = 4; off; off >>= 1) x += __shfl_xor_sync(0xffu, x, off);
        if (t == 0) red[0] = x;
    }
    __syncthreads();
    float mu = red[0] * (1.0f / DM);
    __syncthreads();

    float vs = 0.f;
#pragma unroll
    for (int i = 0; i < 4; i++) { float d = v[i] - mu; vs += d * d; }
#pragma unroll
    for (int off = 16; off; off >>= 1) vs += __shfl_xor_sync(~0u, vs, off);
    if ((t & 31) == 0) red[t >> 5] = vs;
    __syncthreads();
    if (t < 8) {
        float x = red[t];
#pragma unroll
        for (int off = 4; off; off >>= 1) x += __shfl_xor_sync(0xffu, x, off);
        if (t == 0) red[0] = x;
    }
    __syncthreads();
    float rstd = rsqrtf(red[0] * (1.0f / DM) + 1e-5f);

    float4 g4 = *(const float4*)(gamma + t * 4);
    float4 b4 = *(const float4*)(beta  + t * 4);
    float w[4];
    w[0] = (v[0] - mu) * rstd * g4.x + b4.x;
    w[1] = (v[1] - mu) * rstd * g4.y + b4.y;
    w[2] = (v[2] - mu) * rstd * g4.z + b4.z;
    w[3] = (v[3] - mu) * rstd * g4.w + b4.w;
    float4 wf = {w[0], w[1], w[2], w[3]};
    *(float4*)(out + (size_t)row * DM + t * 4) = wf;
    split4(w, oh + (size_t)row * DM + t * 4, ol + (size_t)row * DM + t * 4);
}

// ======================= host driver =======================
extern "C" void kernel_launch(void* const* d_in, const int* in_sizes, int n_in,
                              void* d_out, int out_size)
{
    const float* x    = (const float*)d_in[0];
    const float* Wqkv = (const float*)d_in[1];
    const float* bqkv = (const float*)d_in[2];
    const float* Wo   = (const float*)d_in[3];
    const float* bo   = (const float*)d_in[4];
    const float* W1   = (const float*)d_in[5];
    const float* b1   = (const float*)d_in[6];
    const float* W2   = (const float*)d_in[7];
    const float* b2   = (const float*)d_in[8];
    const float* g1   = (const float*)d_in[9];
    const float* be1  = (const float*)d_in[10];
    const float* g2   = (const float*)d_in[11];
    const float* be2  = (const float*)d_in[12];
    float* out = (float*)d_out;

    float *p_xb, *p_delta;
    __nv_bfloat16 *p_xh, *p_xl, *p_qkvh, *p_qkvl, *p_ah, *p_al, *p_fh, *p_fl;
    __nv_bfloat16 *p_wqh, *p_wql, *p_woh, *p_wol, *p_w1h, *p_w1l, *p_w2h, *p_w2l;
    cudaGetSymbolAddress((void**)&p_xb,  g_xb);
    cudaGetSymbolAddress((void**)&p_delta, g_delta);
    cudaGetSymbolAddress((void**)&p_xh,  g_xh);
    cudaGetSymbolAddress((void**)&p_xl,  g_xl);
    cudaGetSymbolAddress((void**)&p_qkvh, g_qkvh);
    cudaGetSymbolAddress((void**)&p_qkvl, g_qkvl);
    cudaGetSymbolAddress((void**)&p_ah,  g_ah);
    cudaGetSymbolAddress((void**)&p_al,  g_al);
    cudaGetSymbolAddress((void**)&p_fh,  g_fh);
    cudaGetSymbolAddress((void**)&p_fl,  g_fl);
    cudaGetSymbolAddress((void**)&p_wqh, g_wqh);
    cudaGetSymbolAddress((void**)&p_wql, g_wql);
    cudaGetSymbolAddress((void**)&p_woh, g_woh);
    cudaGetSymbolAddress((void**)&p_wol, g_wol);
    cudaGetSymbolAddress((void**)&p_w1h, g_w1h);
    cudaGetSymbolAddress((void**)&p_w1l, g_w1l);
    cudaGetSymbolAddress((void**)&p_w2h, g_w2h);
    cudaGetSymbolAddress((void**)&p_w2l, g_w2l);

    cudaFuncSetAttribute(k_tgemm<0,0>, cudaFuncAttributeMaxDynamicSharedMemorySize, TG_SMEM);
    cudaFuncSetAttribute(k_tgemm<0,1>, cudaFuncAttributeMaxDynamicSharedMemorySize, TG_SMEM);
    cudaFuncSetAttribute(k_tgemm<1,1>, cudaFuncAttributeMaxDynamicSharedMemorySize, TG_SMEM);
    cudaFuncSetAttribute(k_attn, cudaFuncAttributeMaxDynamicSharedMemorySize, ATT_SMEM);

    {
        int ntot = (NL * 3 * DM * DM + NL * DM * DM + NL * DFF * DM + NL * DM * DFF) / 4;
        k_split_all<<<(ntot + 255) / 256, 256>>>(Wqkv, Wo, W1, W2,
            p_wqh, p_wql, p_woh, p_wol, p_w1h, p_w1l, p_w2h, p_w2l);
    }

    const int nElem = MTOT * DM;
    k_in<<<(nElem + 255) / 256, 256>>>(x, p_xb, p_xh, p_xl);

    for (int l = 0; l < NL; l++) {
        // QKV projection -> bf16 hi/lo directly
        k_tgemm<0,1><<<dim3(3 * DM / 128, MTOT / 128), 256, TG_SMEM>>>(
            p_xh, p_xl,
            p_wqh + (size_t)l * 3 * DM * DM, p_wql + (size_t)l * 3 * DM * DM,
            bqkv + (size_t)l * 3 * DM,
            nullptr, p_qkvh, p_qkvl, MTOT, 3 * DM, DM);

        // HMMA flash attention -> bf16 hi/lo
        k_attn<<<dim3(SEQ / 128, NH, BATCH), 256, ATT_SMEM>>>(p_qkvh, p_qkvl, p_ah, p_al);

        // output projection
        k_tgemm<0,0><<<dim3(DM / 128, MTOT / 128), 256, TG_SMEM>>>(
            p_ah, p_al,
            p_woh + (size_t)l * DM * DM, p_wol + (size_t)l * DM * DM,
            bo + (size_t)l * DM,
            p_delta, nullptr, nullptr, MTOT, DM, DM);

        k_ln<<<MTOT, 256>>>(p_xb, p_delta, g1 + (size_t)l * DM, be1 + (size_t)l * DM,
                            p_xb, p_xh, p_xl);

        // FF1 + ReLU -> hi/lo
        k_tgemm<1,1><<<dim3(DFF / 128, MTOT / 128), 256, TG_SMEM>>>(
            p_xh, p_xl,
            p_w1h + (size_t)l * DFF * DM, p_w1l + (size_t)l * DFF * DM,
            b1 + (size_t)l * DFF,
            nullptr, p_fh, p_fl, MTOT, DFF, DM);

        // FF2
        k_tgemm<0,0><<<dim3(DM / 128, MTOT / 128), 256, TG_SMEM>>>(
            p_fh, p_fl,
            p_w2h + (size_t)l * DM * DFF, p_w2l + (size_t)l * DM * DFF,
            b2 + (size_t)l * DM,
            p_delta, nullptr, nullptr, MTOT, DM, DFF);

        k_ln<<<MTOT, 256>>>(p_xb, p_delta, g2 + (size_t)l * DM, be2 + (size_t)l * DM,
                            p_xb, p_xh, p_xl);
    }

    k_out<<<(nElem + 255) / 256, 256>>>(p_xb, out);
}

// round 8
// speedup vs baseline: 2.9193x; 1.0653x over previous
#include <cuda_runtime.h>
#include <cuda_bf16.h>
#include <cstdint>

#define SEQ   1024
#define BATCH 4
#define DM    1024
#define NH    16
#define HD    64
#define DFF   4096
#define NL    4
#define WIN   64
#define MTOT  (SEQ*BATCH)

// ======================= PTX helpers (sm_80+ features only) =======================
__device__ __forceinline__ uint32_t smem_to_u32(const void* p) {
    uint32_t a;
    asm("{ .reg .u64 t; cvta.to.shared.u64 t, %1; cvt.u32.u64 %0, t; }" : "=r"(a) : "l"(p));
    return a;
}
__device__ __forceinline__ void cpa16(uint32_t smem, const void* gmem) {
    asm volatile("cp.async.cg.shared.global [%0], [%1], 16;" :: "r"(smem), "l"(gmem) : "memory");
}
__device__ __forceinline__ void ldsm_x4(uint32_t* r, uint32_t addr) {
    asm volatile("ldmatrix.sync.aligned.m8n8.x4.shared.b16 {%0,%1,%2,%3}, [%4];"
        : "=r"(r[0]), "=r"(r[1]), "=r"(r[2]), "=r"(r[3]) : "r"(addr));
}
__device__ __forceinline__ void ldsm_x2(uint32_t* r, uint32_t addr) {
    asm volatile("ldmatrix.sync.aligned.m8n8.x2.shared.b16 {%0,%1}, [%2];"
        : "=r"(r[0]), "=r"(r[1]) : "r"(addr));
}
__device__ __forceinline__ void ldsm_x2t(uint32_t* r, uint32_t addr) {
    asm volatile("ldmatrix.sync.aligned.m8n8.x2.trans.shared.b16 {%0,%1}, [%2];"
        : "=r"(r[0]), "=r"(r[1]) : "r"(addr));
}
__device__ __forceinline__ void mma16816(float* c, const uint32_t* a, const uint32_t* b) {
    asm volatile(
        "mma.sync.aligned.m16n8k16.row.col.f32.bf16.bf16.f32 "
        "{%0,%1,%2,%3}, {%4,%5,%6,%7}, {%8,%9}, {%0,%1,%2,%3};"
        : "+f"(c[0]), "+f"(c[1]), "+f"(c[2]), "+f"(c[3])
        : "r"(a[0]), "r"(a[1]), "r"(a[2]), "r"(a[3]), "r"(b[0]), "r"(b[1]));
}

// ======================= scratch (device globals) =======================
__device__ __align__(256) float          g_xb   [MTOT * DM];
__device__ __align__(256) __nv_bfloat16  g_xh   [MTOT * DM];
__device__ __align__(256) __nv_bfloat16  g_xl   [MTOT * DM];
__device__ __align__(256) __nv_bfloat16  g_qkvh [MTOT * 3 * DM];
__device__ __align__(256) __nv_bfloat16  g_qkvl [MTOT * 3 * DM];
__device__ __align__(256) __nv_bfloat16  g_ah   [MTOT * DM];
__device__ __align__(256) __nv_bfloat16  g_al   [MTOT * DM];
__device__ __align__(256) float          g_delta[MTOT * DM];
__device__ __align__(256) __nv_bfloat16  g_fh   [MTOT * DFF];
__device__ __align__(256) __nv_bfloat16  g_fl   [MTOT * DFF];
__device__ __align__(256) __nv_bfloat16  g_wqh  [NL * 3 * DM * DM];
__device__ __align__(256) __nv_bfloat16  g_wql  [NL * 3 * DM * DM];
__device__ __align__(256) __nv_bfloat16  g_woh  [NL * DM * DM];
__device__ __align__(256) __nv_bfloat16  g_wol  [NL * DM * DM];
__device__ __align__(256) __nv_bfloat16  g_w1h  [NL * DFF * DM];
__device__ __align__(256) __nv_bfloat16  g_w1l  [NL * DFF * DM];
__device__ __align__(256) __nv_bfloat16  g_w2h  [NL * DM * DFF];
__device__ __align__(256) __nv_bfloat16  g_w2l  [NL * DM * DFF];

__device__ __forceinline__ void split1(float v, __nv_bfloat16& h, __nv_bfloat16& l) {
    h = __float2bfloat16(v);
    l = __float2bfloat16(v - __bfloat162float(h));
}
__device__ __forceinline__ void split4(const float* v, __nv_bfloat16* hp, __nv_bfloat16* lp) {
    __nv_bfloat16 h0, h1, h2, h3, l0, l1, l2, l3;
    split1(v[0], h0, l0); split1(v[1], h1, l1); split1(v[2], h2, l2); split1(v[3], h3, l3);
    __nv_bfloat162 hh0; hh0.x = h0; hh0.y = h1;
    __nv_bfloat162 hh1; hh1.x = h2; hh1.y = h3;
    __nv_bfloat162 ll0; ll0.x = l0; ll0.y = l1;
    __nv_bfloat162 ll1; ll1.x = l2; ll1.y = l3;
    *(__nv_bfloat162*)(hp)     = hh0;
    *(__nv_bfloat162*)(hp + 2) = hh1;
    *(__nv_bfloat162*)(lp)     = ll0;
    *(__nv_bfloat162*)(lp + 2) = ll1;
}
__device__ __forceinline__ void psplit2(float p0, float p1, uint32_t& hi, uint32_t& lo) {
    __nv_bfloat16 h0 = __float2bfloat16(p0), h1 = __float2bfloat16(p1);
    __nv_bfloat16 r0 = __float2bfloat16(p0 - __bfloat162float(h0));
    __nv_bfloat16 r1 = __float2bfloat16(p1 - __bfloat162float(h1));
    __nv_bfloat162 H; H.x = h0; H.y = h1;
    __nv_bfloat162 L; L.x = r0; L.y = r1;
    hi = *(uint32_t*)&H; lo = *(uint32_t*)&L;
}

// ======================= fused weight split =======================
__global__ void k_split_all(const float* __restrict__ Wqkv, const float* __restrict__ Wo,
                            const float* __restrict__ W1,   const float* __restrict__ W2,
                            __nv_bfloat16* wqh, __nv_bfloat16* wql,
                            __nv_bfloat16* woh, __nv_bfloat16* wol,
                            __nv_bfloat16* w1h, __nv_bfloat16* w1l,
                            __nv_bfloat16* w2h, __nv_bfloat16* w2l)
{
    const int N0 = NL * 3 * DM * DM / 4;
    const int N1 = NL * DM * DM / 4;
    const int N2 = NL * DFF * DM / 4;
    const int N3 = NL * DM * DFF / 4;
    int i = blockIdx.x * blockDim.x + threadIdx.x;
    const float* s; __nv_bfloat16 *h, *l; int j;
    if (i < N0)                { s = Wqkv; h = wqh; l = wql; j = i; }
    else if (i < N0+N1)        { s = Wo;   h = woh; l = wol; j = i - N0; }
    else if (i < N0+N1+N2)     { s = W1;   h = w1h; l = w1l; j = i - N0 - N1; }
    else if (i < N0+N1+N2+N3)  { s = W2;   h = w2h; l = w2l; j = i - N0 - N1 - N2; }
    else return;
    float v[4];
    *(float4*)v = *(const float4*)(s + (size_t)j * 4);
    split4(v, h + (size_t)j * 4, l + (size_t)j * 4);
}

// ======================= layout transposes =======================
__global__ void k_in(const float* __restrict__ x, float* __restrict__ xb,
                     __nv_bfloat16* __restrict__ xh, __nv_bfloat16* __restrict__ xl) {
    int idx = blockIdx.x * blockDim.x + threadIdx.x;
    if (idx >= MTOT * DM) return;
    int kcol = idx % DM;
    int row  = idx / DM;
    int b = row / SEQ, s = row % SEQ;
    float v = x[((size_t)(s * BATCH + b)) * DM + kcol];
    xb[idx] = v;
    __nv_bfloat16 h, l; split1(v, h, l);
    xh[idx] = h; xl[idx] = l;
}

__global__ void k_out(const float* __restrict__ xb, float* __restrict__ out) {
    int idx = blockIdx.x * blockDim.x + threadIdx.x;
    if (idx >= MTOT * DM) return;
    int kcol = idx % DM;
    int r    = idx / DM;
    int b = r % BATCH, s = r / BATCH;
    out[idx] = xb[((size_t)(b * SEQ + s)) * DM + kcol];
}

// ======================= HMMA GEMM (mma.sync bf16, 3-term split) =======================
// 128x128 tile, K-chunk 64, 3-stage cp.async pipeline, single sync/chunk,
// A-fragments loaded once per ks and reused across the 3 split terms.
#define PAD    72
#define TILE_B (128 * PAD * 2)
#define STGB   (4 * TILE_B)
#define NSTG   3
#define TG_SMEM (NSTG * STGB)          // 221184 B

template<int RELU, int SPLIT>
__global__ void __launch_bounds__(256, 1)
k_tgemm(const __nv_bfloat16* __restrict__ Ah, const __nv_bfloat16* __restrict__ Al,
        const __nv_bfloat16* __restrict__ Bh, const __nv_bfloat16* __restrict__ Bl,
        const float* __restrict__ bias,
        float* __restrict__ Cf, __nv_bfloat16* __restrict__ Ch, __nv_bfloat16* __restrict__ Cl,
        int M, int N, int K)
{
    extern __shared__ char dsm[];
    const uint32_t sbase = smem_to_u32(dsm);
    const int tid  = threadIdx.x;
    const int lane = tid & 31;
    const int wid  = tid >> 5;
    const int wm   = wid >> 2;
    const int wn   = wid & 3;
    const int m0 = blockIdx.y * 128;
    const int n0 = blockIdx.x * 128;
    const int nch = K >> 6;

    const __nv_bfloat16* srcs[4] = {Ah, Al, Bh, Bl};
    const int rowbase[4] = {m0, m0, n0, n0};

    float acc[4][4][4];
#pragma unroll
    for (int mt = 0; mt < 4; mt++)
#pragma unroll
        for (int nt = 0; nt < 4; nt++)
#pragma unroll
            for (int i = 0; i < 4; i++) acc[mt][nt][i] = 0.f;

    const uint32_t aoff = ((wm * 64 + (lane & 15)) * PAD + (lane >> 4) * 8) * 2;
    const uint32_t boff = ((wn * 32 + (lane & 7)) * PAD + ((lane >> 3) & 1) * 8) * 2;

    // prologue: chunks 0,1 -> stages 0,1
#pragma unroll
    for (int cp = 0; cp < 2; cp++) {
        uint32_t stg = sbase + cp * STGB;
#pragma unroll
        for (int i = 0; i < 16; i++) {
            int idx = tid + i * 256;
            int t = idx >> 10, r = (idx & 1023) >> 3, c = idx & 7;
            cpa16(stg + t * TILE_B + r * (PAD * 2) + c * 16,
                  srcs[t] + (size_t)(rowbase[t] + r) * K + cp * 64 + c * 8);
        }
        asm volatile("cp.async.commit_group;" ::: "memory");
    }

    int stage = 0;
    for (int cch = 0; cch < nch; cch++) {
        asm volatile("cp.async.wait_group 1;" ::: "memory");   // chunk cch resident
        __syncthreads();                                        // everyone done with stage (cch-1)%3

        // issue chunk cch+2 into stage (cch+2)%3 == (cch-1)%3 — safe after the barrier
        if (cch + 2 < nch) {
            int sn = stage + 2; if (sn >= NSTG) sn -= NSTG;
            uint32_t stg = sbase + sn * STGB;
#pragma unroll
            for (int i = 0; i < 16; i++) {
                int idx = tid + i * 256;
                int t = idx >> 10, r = (idx & 1023) >> 3, c = idx & 7;
                cpa16(stg + t * TILE_B + r * (PAD * 2) + c * 16,
                      srcs[t] + (size_t)(rowbase[t] + r) * K + (cch + 2) * 64 + c * 8);
            }
            asm volatile("cp.async.commit_group;" ::: "memory");
        }

        const uint32_t stg = sbase + stage * STGB;
        const uint32_t Ah_s = stg,              Al_s = stg + TILE_B;
        const uint32_t Bh_s = stg + 2 * TILE_B, Bl_s = stg + 3 * TILE_B;

#pragma unroll
        for (int ks = 0; ks < 4; ks++) {
            uint32_t ah[4][4], al[4][4];
#pragma unroll
            for (int mt = 0; mt < 4; mt++) {
                uint32_t off = aoff + (mt * 16 * PAD + ks * 16) * 2;
                ldsm_x4(ah[mt], Ah_s + off);
                ldsm_x4(al[mt], Al_s + off);
            }
#pragma unroll
            for (int nt = 0; nt < 4; nt++) {
                uint32_t bh[2], bl[2];
                uint32_t off = boff + (nt * 8 * PAD + ks * 16) * 2;
                ldsm_x2(bh, Bh_s + off);
                ldsm_x2(bl, Bl_s + off);
#pragma unroll
                for (int mt = 0; mt < 4; mt++) {
                    mma16816(acc[mt][nt], ah[mt], bh);
                    mma16816(acc[mt][nt], ah[mt], bl);
                    mma16816(acc[mt][nt], al[mt], bh);
                }
            }
        }
        stage++; if (stage >= NSTG) stage = 0;
    }

    const int r0 = m0 + wm * 64 + (lane >> 2);
    const int c0 = n0 + wn * 32 + 2 * (lane & 3);
#pragma unroll
    for (int mt = 0; mt < 4; mt++) {
#pragma unroll
        for (int nt = 0; nt < 4; nt++) {
            int col = c0 + nt * 8;
            float b0 = bias[col], b1 = bias[col + 1];
#pragma unroll
            for (int half = 0; half < 2; half++) {
                int row = r0 + mt * 16 + half * 8;
                float v0 = acc[mt][nt][2 * half + 0] + b0;
                float v1 = acc[mt][nt][2 * half + 1] + b1;
                if (RELU) { v0 = fmaxf(v0, 0.f); v1 = fmaxf(v1, 0.f); }
                size_t off = (size_t)row * N + col;
                if (!SPLIT) {
                    float2 w = {v0, v1};
                    *(float2*)(Cf + off) = w;
                } else {
                    uint32_t hi, lo;
                    psplit2(v0, v1, hi, lo);
                    *(uint32_t*)(Ch + off) = hi;
                    *(uint32_t*)(Cl + off) = lo;
                }
            }
        }
    }
}

// ======================= HMMA banded flash attention =======================
#define AP     72
#define AROWB  (AP * 2)
#define QTILEB (128 * AROWB)
#define ATILEB (64 * AROWB)
#define ASTGB  (4 * ATILEB)
#define ATT_SMEM (2 * QTILEB + 2 * ASTGB)

__global__ void __launch_bounds__(256, 1)
k_attn(const __nv_bfloat16* __restrict__ qh, const __nv_bfloat16* __restrict__ ql,
       __nv_bfloat16* __restrict__ ah, __nv_bfloat16* __restrict__ al)
{
    extern __shared__ char asm_[];
    const uint32_t sbase = smem_to_u32(asm_);
    const uint32_t Qh_s = sbase, Ql_s = sbase + QTILEB;
    const uint32_t stg0 = sbase + 2 * QTILEB;

    const int tid = threadIdx.x;
    const int lane = tid & 31;
    const int w = tid >> 5;
    const int Qb = blockIdx.x, h = blockIdx.y, b = blockIdx.z;
    const int nch = min(16, 2 * Qb + 3);
    const size_t rstr = 3 * DM;
    const size_t rowoff0 = (size_t)(b * SEQ) * rstr + h * HD;

#pragma unroll
    for (int i = 0; i < 8; i++) {
        int lin = i * 256 + tid;
        int hl = lin >> 10, loc = lin & 1023;
        int r = loc >> 3, p = loc & 7;
        const __nv_bfloat16* src = (hl ? ql : qh) + rowoff0 + (size_t)(Qb * 128 + r) * rstr + p * 8;
        cpa16((hl ? Ql_s : Qh_s) + r * AROWB + p * 16, src);
    }
#pragma unroll
    for (int i = 0; i < 8; i++) {
        int lin = i * 256 + tid;
        int t = lin >> 9, loc = lin & 511;
        int r = loc >> 3, p = loc & 7;
        const __nv_bfloat16* src = ((t & 1) ? ql : qh) + rowoff0
            + (size_t)(0 + r) * rstr + ((t < 2) ? DM : 2 * DM) + p * 8;
        cpa16(stg0 + t * ATILEB + r * AROWB + p * 16, src);
    }
    asm volatile("cp.async.commit_group;" ::: "memory");
    asm volatile("cp.async.wait_group 0;" ::: "memory");
    __syncthreads();

    uint32_t qfh[4][4], qfl[4][4];
    {
        uint32_t qaddr = ((w * 16 + (lane & 15)) * AROWB) + (lane >> 4) * 16;
#pragma unroll
        for (int ks = 0; ks < 4; ks++) {
            ldsm_x4(qfh[ks], Qh_s + qaddr + ks * 32);
            ldsm_x4(qfl[ks], Ql_s + qaddr + ks * 32);
        }
    }

    float oacc[8][4];
#pragma unroll
    for (int nt = 0; nt < 8; nt++)
#pragma unroll
        for (int i = 0; i < 4; i++) oacc[nt][i] = 0.f;
    float m0 = -1e30f, m1 = -1e30f, l0 = 0.f, l1 = 0.f;

    const int q0 = Qb * 128 + w * 16 + (lane >> 2);
    const int lim0 = q0 + WIN, lim1 = q0 + 8 + WIN;
    const uint32_t kfoff = ((lane & 7) * AROWB) + ((lane >> 3) & 1) * 16;
    const uint32_t vfoff = ((lane & 15) * AROWB);

    for (int c = 0; c < nch; c++) {
        if (c > 0) {
            asm volatile("cp.async.wait_group 0;" ::: "memory");
            __syncthreads();
        }
        if (c + 1 < nch) {
            uint32_t stg = stg0 + ((c + 1) & 1) * ASTGB;
#pragma unroll
            for (int i = 0; i < 8; i++) {
                int lin = i * 256 + tid;
                int t = lin >> 9, loc = lin & 511;
                int r = loc >> 3, p = loc & 7;
                const __nv_bfloat16* src = ((t & 1) ? ql : qh) + rowoff0
                    + (size_t)((c + 1) * 64 + r) * rstr + ((t < 2) ? DM : 2 * DM) + p * 8;
                cpa16(stg + t * ATILEB + r * AROWB + p * 16, src);
            }
        }
        asm volatile("cp.async.commit_group;" ::: "memory");

        const uint32_t stg = stg0 + (c & 1) * ASTGB;
        const uint32_t Kh_s = stg, Kl_s = stg + ATILEB;
        const uint32_t Vh_s = stg + 2 * ATILEB, Vl_s = stg + 3 * ATILEB;

        float sacc[8][4];
#pragma unroll
        for (int nt = 0; nt < 8; nt++)
#pragma unroll
            for (int i = 0; i < 4; i++) sacc[nt][i] = 0.f;
#pragma unroll
        for (int ks = 0; ks < 4; ks++) {
#pragma unroll
            for (int nt = 0; nt < 8; nt++) {
                uint32_t kh[2], kl[2];
                uint32_t off = nt * 8 * AROWB + kfoff + ks * 32;
                ldsm_x2(kh, Kh_s + off);
                ldsm_x2(kl, Kl_s + off);
                mma16816(sacc[nt], qfh[ks], kh);
                mma16816(sacc[nt], qfh[ks], kl);
                mma16816(sacc[nt], qfl[ks], kh);
            }
        }

        const float scale = 0.125f;
        float mc0 = -1e30f, mc1 = -1e30f;
        const bool domask = (c >= 2 * Qb + 1);
        const int jb = c * 64 + 2 * (lane & 3);
#pragma unroll
        for (int nt = 0; nt < 8; nt++) {
            int j0 = jb + nt * 8, j1 = j0 + 1;
            float s0 = sacc[nt][0] * scale, s1 = sacc[nt][1] * scale;
            float s2 = sacc[nt][2] * scale, s3 = sacc[nt][3] * scale;
            if (domask) {
                if (j0 > lim0) s0 = -1e30f;
                if (j1 > lim0) s1 = -1e30f;
                if (j0 > lim1) s2 = -1e30f;
                if (j1 > lim1) s3 = -1e30f;
            }
            sacc[nt][0] = s0; sacc[nt][1] = s1; sacc[nt][2] = s2; sacc[nt][3] = s3;
            mc0 = fmaxf(mc0, fmaxf(s0, s1));
            mc1 = fmaxf(mc1, fmaxf(s2, s3));
        }
        mc0 = fmaxf(mc0, __shfl_xor_sync(~0u, mc0, 1));
        mc0 = fmaxf(mc0, __shfl_xor_sync(~0u, mc0, 2));
        mc1 = fmaxf(mc1, __shfl_xor_sync(~0u, mc1, 1));
        mc1 = fmaxf(mc1, __shfl_xor_sync(~0u, mc1, 2));
        float m0n = fmaxf(m0, mc0), m1n = fmaxf(m1, mc1);
        float a0 = __expf(m0 - m0n), a1 = __expf(m1 - m1n);
        l0 *= a0; l1 *= a1;
#pragma unroll
        for (int nt = 0; nt < 8; nt++) {
            oacc[nt][0] *= a0; oacc[nt][1] *= a0;
            oacc[nt][2] *= a1; oacc[nt][3] *= a1;
        }
#pragma unroll
        for (int nt = 0; nt < 8; nt++) {
            float p0 = __expf(sacc[nt][0] - m0n), p1 = __expf(sacc[nt][1] - m0n);
            float p2 = __expf(sacc[nt][2] - m1n), p3 = __expf(sacc[nt][3] - m1n);
            sacc[nt][0] = p0; sacc[nt][1] = p1; sacc[nt][2] = p2; sacc[nt][3] = p3;
            l0 += p0 + p1; l1 += p2 + p3;
        }
        m0 = m0n; m1 = m1n;

#pragma unroll
        for (int kk = 0; kk < 4; kk++) {
            uint32_t pah[4], pal[4];
            psplit2(sacc[2*kk][0],   sacc[2*kk][1],   pah[0], pal[0]);
            psplit2(sacc[2*kk][2],   sacc[2*kk][3],   pah[1], pal[1]);
            psplit2(sacc[2*kk+1][0], sacc[2*kk+1][1], pah[2], pal[2]);
            psplit2(sacc[2*kk+1][2], sacc[2*kk+1][3], pah[3], pal[3]);
#pragma unroll
            for (int nt = 0; nt < 8; nt++) {
                uint32_t vh[2], vl[2];
                uint32_t off = kk * 16 * AROWB + vfoff + nt * 16;
                ldsm_x2t(vh, Vh_s + off);
                ldsm_x2t(vl, Vl_s + off);
                mma16816(oacc[nt], pah, vh);
                mma16816(oacc[nt], pah, vl);
                mma16816(oacc[nt], pal, vh);
            }
        }
    }

    l0 += __shfl_xor_sync(~0u, l0, 1); l0 += __shfl_xor_sync(~0u, l0, 2);
    l1 += __shfl_xor_sync(~0u, l1, 1); l1 += __shfl_xor_sync(~0u, l1, 2);
    float inv0 = 1.0f / l0, inv1 = 1.0f / l1;
    size_t orow0 = (size_t)(b * SEQ + q0) * DM + h * HD;
    size_t orow1 = orow0 + (size_t)8 * DM;
    int cbase = 2 * (lane & 3);
#pragma unroll
    for (int nt = 0; nt < 8; nt++) {
        int col = cbase + nt * 8;
        uint32_t hi, lo;
        psplit2(oacc[nt][0] * inv0, oacc[nt][1] * inv0, hi, lo);
        *(uint32_t*)(ah + orow0 + col) = hi;
        *(uint32_t*)(al + orow0 + col) = lo;
        psplit2(oacc[nt][2] * inv1, oacc[nt][3] * inv1, hi, lo);
        *(uint32_t*)(ah + orow1 + col) = hi;
        *(uint32_t*)(al + orow1 + col) = lo;
    }
}

// ======================= LayerNorm(resid + delta) -> fp32 + hi/lo =======================
__global__ void __launch_bounds__(256)
k_ln(const float* __restrict__ resid, const float* __restrict__ delta,
     const float* __restrict__ gamma, const float* __restrict__ beta,
     float* __restrict__ out, __nv_bfloat16* __restrict__ oh, __nv_bfloat16* __restrict__ ol)
{
    __shared__ float red[8];
    const int row = blockIdx.x;
    const int t = threadIdx.x;
    const float* rp = resid + (size_t)row * DM;
    const float* dp = delta + (size_t)row * DM;

    float4 rv = *(const float4*)(rp + t * 4);
    float4 dv = *(const float4*)(dp + t * 4);
    float v[4] = {rv.x + dv.x, rv.y + dv.y, rv.z + dv.z, rv.w + dv.w};

    float s = v[0] + v[1] + v[2] + v[3];
#pragma unroll
    for (int off = 16; off; off >>= 1) s += __shfl_xor_sync(~0u, s, off);
    if ((t & 31) == 0) red[t >> 5] = s;
    __syncthreads();
    if (t < 8) {
        float x = red[t];
#pragma unroll
        for (int off = 4; off; off >>= 1) x += __shfl_xor_sync(0xffu, x, off);
        if (t == 0) red[0] = x;
    }
    __syncthreads();
    float mu = red[0] * (1.0f / DM);
    __syncthreads();

    float vs = 0.f;
#pragma unroll
    for (int i = 0; i < 4; i++) { float d = v[i] - mu; vs += d * d; }
#pragma unroll
    for (int off = 16; off; off >>= 1) vs += __shfl_xor_sync(~0u, vs, off);
    if ((t & 31) == 0) red[t >> 5] = vs;
    __syncthreads();
    if (t < 8) {
        float x = red[t];
#pragma unroll
        for (int off = 4; off; off >>= 1) x += __shfl_xor_sync(0xffu, x, off);
        if (t == 0) red[0] = x;
    }
    __syncthreads();
    float rstd = rsqrtf(red[0] * (1.0f / DM) + 1e-5f);

    float4 g4 = *(const float4*)(gamma + t * 4);
    float4 b4 = *(const float4*)(beta  + t * 4);
    float w[4];
    w[0] = (v[0] - mu) * rstd * g4.x + b4.x;
    w[1] = (v[1] - mu) * rstd * g4.y + b4.y;
    w[2] = (v[2] - mu) * rstd * g4.z + b4.z;
    w[3] = (v[3] - mu) * rstd * g4.w + b4.w;
    float4 wf = {w[0], w[1], w[2], w[3]};
    *(float4*)(out + (size_t)row * DM + t * 4) = wf;
    split4(w, oh + (size_t)row * DM + t * 4, ol + (size_t)row * DM + t * 4);
}

// ======================= host driver =======================
extern "C" void kernel_launch(void* const* d_in, const int* in_sizes, int n_in,
                              void* d_out, int out_size)
{
    const float* x    = (const float*)d_in[0];
    const float* Wqkv = (const float*)d_in[1];
    const float* bqkv = (const float*)d_in[2];
    const float* Wo   = (const float*)d_in[3];
    const float* bo   = (const float*)d_in[4];
    const float* W1   = (const float*)d_in[5];
    const float* b1   = (const float*)d_in[6];
    const float* W2   = (const float*)d_in[7];
    const float* b2   = (const float*)d_in[8];
    const float* g1   = (const float*)d_in[9];
    const float* be1  = (const float*)d_in[10];
    const float* g2   = (const float*)d_in[11];
    const float* be2  = (const float*)d_in[12];
    float* out = (float*)d_out;

    float *p_xb, *p_delta;
    __nv_bfloat16 *p_xh, *p_xl, *p_qkvh, *p_qkvl, *p_ah, *p_al, *p_fh, *p_fl;
    __nv_bfloat16 *p_wqh, *p_wql, *p_woh, *p_wol, *p_w1h, *p_w1l, *p_w2h, *p_w2l;
    cudaGetSymbolAddress((void**)&p_xb,  g_xb);
    cudaGetSymbolAddress((void**)&p_delta, g_delta);
    cudaGetSymbolAddress((void**)&p_xh,  g_xh);
    cudaGetSymbolAddress((void**)&p_xl,  g_xl);
    cudaGetSymbolAddress((void**)&p_qkvh, g_qkvh);
    cudaGetSymbolAddress((void**)&p_qkvl, g_qkvl);
    cudaGetSymbolAddress((void**)&p_ah,  g_ah);
    cudaGetSymbolAddress((void**)&p_al,  g_al);
    cudaGetSymbolAddress((void**)&p_fh,  g_fh);
    cudaGetSymbolAddress((void**)&p_fl,  g_fl);
    cudaGetSymbolAddress((void**)&p_wqh, g_wqh);
    cudaGetSymbolAddress((void**)&p_wql, g_wql);
    cudaGetSymbolAddress((void**)&p_woh, g_woh);
    cudaGetSymbolAddress((void**)&p_wol, g_wol);
    cudaGetSymbolAddress((void**)&p_w1h, g_w1h);
    cudaGetSymbolAddress((void**)&p_w1l, g_w1l);
    cudaGetSymbolAddress((void**)&p_w2h, g_w2h);
    cudaGetSymbolAddress((void**)&p_w2l, g_w2l);

    cudaFuncSetAttribute(k_tgemm<0,0>, cudaFuncAttributeMaxDynamicSharedMemorySize, TG_SMEM);
    cudaFuncSetAttribute(k_tgemm<0,1>, cudaFuncAttributeMaxDynamicSharedMemorySize, TG_SMEM);
    cudaFuncSetAttribute(k_tgemm<1,1>, cudaFuncAttributeMaxDynamicSharedMemorySize, TG_SMEM);
    cudaFuncSetAttribute(k_attn, cudaFuncAttributeMaxDynamicSharedMemorySize, ATT_SMEM);

    {
        int ntot = (NL * 3 * DM * DM + NL * DM * DM + NL * DFF * DM + NL * DM * DFF) / 4;
        k_split_all<<<(ntot + 255) / 256, 256>>>(Wqkv, Wo, W1, W2,
            p_wqh, p_wql, p_woh, p_wol, p_w1h, p_w1l, p_w2h, p_w2l);
    }

    const int nElem = MTOT * DM;
    k_in<<<(nElem + 255) / 256, 256>>>(x, p_xb, p_xh, p_xl);

    for (int l = 0; l < NL; l++) {
        k_tgemm<0,1><<<dim3(3 * DM / 128, MTOT / 128), 256, TG_SMEM>>>(
            p_xh, p_xl,
            p_wqh + (size_t)l * 3 * DM * DM, p_wql + (size_t)l * 3 * DM * DM,
            bqkv + (size_t)l * 3 * DM,
            nullptr, p_qkvh, p_qkvl, MTOT, 3 * DM, DM);

        k_attn<<<dim3(SEQ / 128, NH, BATCH), 256, ATT_SMEM>>>(p_qkvh, p_qkvl, p_ah, p_al);

        k_tgemm<0,0><<<dim3(DM / 128, MTOT / 128), 256, TG_SMEM>>>(
            p_ah, p_al,
            p_woh + (size_t)l * DM * DM, p_wol + (size_t)l * DM * DM,
            bo + (size_t)l * DM,
            p_delta, nullptr, nullptr, MTOT, DM, DM);

        k_ln<<<MTOT, 256>>>(p_xb, p_delta, g1 + (size_t)l * DM, be1 + (size_t)l * DM,
                            p_xb, p_xh, p_xl);

        k_tgemm<1,1><<<dim3(DFF / 128, MTOT / 128), 256, TG_SMEM>>>(
            p_xh, p_xl,
            p_w1h + (size_t)l * DFF * DM, p_w1l + (size_t)l * DFF * DM,
            b1 + (size_t)l * DFF,
            nullptr, p_fh, p_fl, MTOT, DFF, DM);

        k_tgemm<0,0><<<dim3(DM / 128, MTOT / 128), 256, TG_SMEM>>>(
            p_fh, p_fl,
            p_w2h + (size_t)l * DM * DFF, p_w2l + (size_t)l * DM * DFF,
            b2 + (size_t)l * DM,
            p_delta, nullptr, nullptr, MTOT, DM, DFF);

        k_ln<<<MTOT, 256>>>(p_xb, p_delta, g2 + (size_t)l * DM, be2 + (size_t)l * DM,
                            p_xb, p_xh, p_xl);
    }

    k_out<<<(nElem + 255) / 256, 256>>>(p_xb, out);
}

// round 9
// speedup vs baseline: 2.9840x; 1.0221x over previous
#include <cuda_runtime.h>
#include <cuda_bf16.h>
#include <cstdint>

#define SEQ   1024
#define BATCH 4
#define DM    1024
#define NH    16
#define HD    64
#define DFF   4096
#define NL    4
#define WIN   64
#define MTOT  (SEQ*BATCH)

// ======================= PTX helpers (sm_80+ features only) =======================
__device__ __forceinline__ uint32_t smem_to_u32(const void* p) {
    uint32_t a;
    asm("{ .reg .u64 t; cvta.to.shared.u64 t, %1; cvt.u32.u64 %0, t; }" : "=r"(a) : "l"(p));
    return a;
}
__device__ __forceinline__ void cpa16(uint32_t smem, const void* gmem) {
    asm volatile("cp.async.cg.shared.global [%0], [%1], 16;" :: "r"(smem), "l"(gmem) : "memory");
}
__device__ __forceinline__ void ldsm_x4(uint32_t* r, uint32_t addr) {
    asm volatile("ldmatrix.sync.aligned.m8n8.x4.shared.b16 {%0,%1,%2,%3}, [%4];"
        : "=r"(r[0]), "=r"(r[1]), "=r"(r[2]), "=r"(r[3]) : "r"(addr));
}
__device__ __forceinline__ void ldsm_x2(uint32_t* r, uint32_t addr) {
    asm volatile("ldmatrix.sync.aligned.m8n8.x2.shared.b16 {%0,%1}, [%2];"
        : "=r"(r[0]), "=r"(r[1]) : "r"(addr));
}
__device__ __forceinline__ void ldsm_x2t(uint32_t* r, uint32_t addr) {
    asm volatile("ldmatrix.sync.aligned.m8n8.x2.trans.shared.b16 {%0,%1}, [%2];"
        : "=r"(r[0]), "=r"(r[1]) : "r"(addr));
}
__device__ __forceinline__ void mma16816(float* c, const uint32_t* a, const uint32_t* b) {
    asm volatile(
        "mma.sync.aligned.m16n8k16.row.col.f32.bf16.bf16.f32 "
        "{%0,%1,%2,%3}, {%4,%5,%6,%7}, {%8,%9}, {%0,%1,%2,%3};"
        : "+f"(c[0]), "+f"(c[1]), "+f"(c[2]), "+f"(c[3])
        : "r"(a[0]), "r"(a[1]), "r"(a[2]), "r"(a[3]), "r"(b[0]), "r"(b[1]));
}

// ======================= scratch (device globals) =======================
__device__ __align__(256) float          g_xb   [MTOT * DM];
__device__ __align__(256) __nv_bfloat16  g_xh   [MTOT * DM];
__device__ __align__(256) __nv_bfloat16  g_xl   [MTOT * DM];
__device__ __align__(256) __nv_bfloat16  g_qkvh [MTOT * 3 * DM];
__device__ __align__(256) __nv_bfloat16  g_qkvl [MTOT * 3 * DM];
__device__ __align__(256) __nv_bfloat16  g_ah   [MTOT * DM];
__device__ __align__(256) __nv_bfloat16  g_al   [MTOT * DM];
__device__ __align__(256) float          g_delta[MTOT * DM];
__device__ __align__(256) __nv_bfloat16  g_fh   [MTOT * DFF];
__device__ __align__(256) __nv_bfloat16  g_fl   [MTOT * DFF];
__device__ __align__(256) __nv_bfloat16  g_wqh  [NL * 3 * DM * DM];
__device__ __align__(256) __nv_bfloat16  g_wql  [NL * 3 * DM * DM];
__device__ __align__(256) __nv_bfloat16  g_woh  [NL * DM * DM];
__device__ __align__(256) __nv_bfloat16  g_wol  [NL * DM * DM];
__device__ __align__(256) __nv_bfloat16  g_w1h  [NL * DFF * DM];
__device__ __align__(256) __nv_bfloat16  g_w1l  [NL * DFF * DM];
__device__ __align__(256) __nv_bfloat16  g_w2h  [NL * DM * DFF];
__device__ __align__(256) __nv_bfloat16  g_w2l  [NL * DM * DFF];

__device__ __forceinline__ void split1(float v, __nv_bfloat16& h, __nv_bfloat16& l) {
    h = __float2bfloat16(v);
    l = __float2bfloat16(v - __bfloat162float(h));
}
__device__ __forceinline__ void split4(const float* v, __nv_bfloat16* hp, __nv_bfloat16* lp) {
    __nv_bfloat16 h0, h1, h2, h3, l0, l1, l2, l3;
    split1(v[0], h0, l0); split1(v[1], h1, l1); split1(v[2], h2, l2); split1(v[3], h3, l3);
    __nv_bfloat162 hh0; hh0.x = h0; hh0.y = h1;
    __nv_bfloat162 hh1; hh1.x = h2; hh1.y = h3;
    __nv_bfloat162 ll0; ll0.x = l0; ll0.y = l1;
    __nv_bfloat162 ll1; ll1.x = l2; ll1.y = l3;
    *(__nv_bfloat162*)(hp)     = hh0;
    *(__nv_bfloat162*)(hp + 2) = hh1;
    *(__nv_bfloat162*)(lp)     = ll0;
    *(__nv_bfloat162*)(lp + 2) = ll1;
}
__device__ __forceinline__ void psplit2(float p0, float p1, uint32_t& hi, uint32_t& lo) {
    __nv_bfloat16 h0 = __float2bfloat16(p0), h1 = __float2bfloat16(p1);
    __nv_bfloat16 r0 = __float2bfloat16(p0 - __bfloat162float(h0));
    __nv_bfloat16 r1 = __float2bfloat16(p1 - __bfloat162float(h1));
    __nv_bfloat162 H; H.x = h0; H.y = h1;
    __nv_bfloat162 L; L.x = r0; L.y = r1;
    hi = *(uint32_t*)&H; lo = *(uint32_t*)&L;
}

// ======================= fused weight split =======================
__global__ void k_split_all(const float* __restrict__ Wqkv, const float* __restrict__ Wo,
                            const float* __restrict__ W1,   const float* __restrict__ W2,
                            __nv_bfloat16* wqh, __nv_bfloat16* wql,
                            __nv_bfloat16* woh, __nv_bfloat16* wol,
                            __nv_bfloat16* w1h, __nv_bfloat16* w1l,
                            __nv_bfloat16* w2h, __nv_bfloat16* w2l)
{
    const int N0 = NL * 3 * DM * DM / 4;
    const int N1 = NL * DM * DM / 4;
    const int N2 = NL * DFF * DM / 4;
    const int N3 = NL * DM * DFF / 4;
    int i = blockIdx.x * blockDim.x + threadIdx.x;
    const float* s; __nv_bfloat16 *h, *l; int j;
    if (i < N0)                { s = Wqkv; h = wqh; l = wql; j = i; }
    else if (i < N0+N1)        { s = Wo;   h = woh; l = wol; j = i - N0; }
    else if (i < N0+N1+N2)     { s = W1;   h = w1h; l = w1l; j = i - N0 - N1; }
    else if (i < N0+N1+N2+N3)  { s = W2;   h = w2h; l = w2l; j = i - N0 - N1 - N2; }
    else return;
    float v[4];
    *(float4*)v = *(const float4*)(s + (size_t)j * 4);
    split4(v, h + (size_t)j * 4, l + (size_t)j * 4);
}

// ======================= layout transposes =======================
__global__ void k_in(const float* __restrict__ x, float* __restrict__ xb,
                     __nv_bfloat16* __restrict__ xh, __nv_bfloat16* __restrict__ xl) {
    int idx = blockIdx.x * blockDim.x + threadIdx.x;
    if (idx >= MTOT * DM) return;
    int kcol = idx % DM;
    int row  = idx / DM;
    int b = row / SEQ, s = row % SEQ;
    float v = x[((size_t)(s * BATCH + b)) * DM + kcol];
    xb[idx] = v;
    __nv_bfloat16 h, l; split1(v, h, l);
    xh[idx] = h; xl[idx] = l;
}

__global__ void k_out(const float* __restrict__ xb, float* __restrict__ out) {
    int idx = blockIdx.x * blockDim.x + threadIdx.x;
    if (idx >= MTOT * DM) return;
    int kcol = idx % DM;
    int r    = idx / DM;
    int b = r % BATCH, s = r / BATCH;
    out[idx] = xb[((size_t)(b * SEQ + s)) * DM + kcol];
}

// ======================= HMMA GEMM: 256x128 tile, 3-term bf16 split =======================
// 8 warps in a 4x2 grid, each computing 64x64. K-chunk 64, 2-stage pipeline.
#define PAD    72
#define AT_B   (256 * PAD * 2)        // 36864 (one 256-row tile)
#define BT_B   (128 * PAD * 2)        // 18432 (one 128-row tile)
#define STG_B  (2 * AT_B + 2 * BT_B)  // 110592
#define TG_SMEM (2 * STG_B)           // 221184

template<int RELU, int SPLIT>
__global__ void __launch_bounds__(256, 1)
k_tgemm(const __nv_bfloat16* __restrict__ Ah, const __nv_bfloat16* __restrict__ Al,
        const __nv_bfloat16* __restrict__ Bh, const __nv_bfloat16* __restrict__ Bl,
        const float* __restrict__ bias,
        float* __restrict__ Cf, __nv_bfloat16* __restrict__ Ch, __nv_bfloat16* __restrict__ Cl,
        int M, int N, int K)
{
    extern __shared__ char dsm[];
    const uint32_t sbase = smem_to_u32(dsm);
    const int tid  = threadIdx.x;
    const int lane = tid & 31;
    const int wid  = tid >> 5;
    const int wm   = wid >> 1;          // 0..3 (64-row slab)
    const int wn   = wid & 1;           // 0..1 (64-col slab)
    const int m0 = blockIdx.y * 256;
    const int n0 = blockIdx.x * 128;
    const int nch = K >> 6;

    float acc[4][8][4];
#pragma unroll
    for (int mt = 0; mt < 4; mt++)
#pragma unroll
        for (int nt = 0; nt < 8; nt++)
#pragma unroll
            for (int i = 0; i < 4; i++) acc[mt][nt][i] = 0.f;

    const uint32_t aoff = ((wm * 64 + (lane & 15)) * PAD + (lane >> 4) * 8) * 2;
    const uint32_t boff = ((wn * 64 + (lane & 7)) * PAD + ((lane >> 3) & 1) * 8) * 2;

    // tile loader: 6144 x 16B pieces per chunk, 24 per thread
    auto load_chunk = [&](int cc, int s) {
        uint32_t stg = sbase + s * STG_B;
#pragma unroll
        for (int i = 0; i < 24; i++) {
            int idx = tid + i * 256;
            if (idx < 4096) {                        // A tiles (hi, lo)
                int t = idx >> 11, loc = idx & 2047;
                int r = loc >> 3, c = loc & 7;
                cpa16(stg + t * AT_B + r * (PAD * 2) + c * 16,
                      (t ? Al : Ah) + (size_t)(m0 + r) * K + cc * 64 + c * 8);
            } else {                                 // B tiles (hi, lo)
                int j = idx - 4096;
                int t = j >> 10, loc = j & 1023;
                int r = loc >> 3, c = loc & 7;
                cpa16(stg + 2 * AT_B + t * BT_B + r * (PAD * 2) + c * 16,
                      (t ? Bl : Bh) + (size_t)(n0 + r) * K + cc * 64 + c * 8);
            }
        }
    };

    load_chunk(0, 0);
    asm volatile("cp.async.commit_group;" ::: "memory");

    for (int cch = 0; cch < nch; cch++) {
        __syncthreads();                 // all warps done with stage (cch+1)&1's previous contents
        if (cch + 1 < nch) load_chunk(cch + 1, (cch + 1) & 1);
        asm volatile("cp.async.commit_group;" ::: "memory");
        asm volatile("cp.async.wait_group 1;" ::: "memory");   // chunk cch resident
        __syncthreads();

        const uint32_t stg = sbase + (cch & 1) * STG_B;
        const uint32_t Ah_s = stg, Al_s = stg + AT_B;
        const uint32_t Bh_s = stg + 2 * AT_B, Bl_s = stg + 2 * AT_B + BT_B;

#pragma unroll
        for (int ks = 0; ks < 4; ks++) {
            uint32_t bh[8][2], bl[8][2];
#pragma unroll
            for (int nt = 0; nt < 8; nt++) {
                uint32_t off = boff + (nt * 8 * PAD + ks * 16) * 2;
                ldsm_x2(bh[nt], Bh_s + off);
                ldsm_x2(bl[nt], Bl_s + off);
            }
#pragma unroll
            for (int mt = 0; mt < 4; mt++) {
                uint32_t ah[4], al[4];
                uint32_t off = aoff + (mt * 16 * PAD + ks * 16) * 2;
                ldsm_x4(ah, Ah_s + off);
                ldsm_x4(al, Al_s + off);
#pragma unroll
                for (int nt = 0; nt < 8; nt++) {
                    mma16816(acc[mt][nt], ah, bh[nt]);
                    mma16816(acc[mt][nt], ah, bl[nt]);
                    mma16816(acc[mt][nt], al, bh[nt]);
                }
            }
        }
    }

    const int r0 = m0 + wm * 64 + (lane >> 2);
    const int c0 = n0 + wn * 64 + 2 * (lane & 3);
#pragma unroll
    for (int mt = 0; mt < 4; mt++) {
#pragma unroll
        for (int nt = 0; nt < 8; nt++) {
            int col = c0 + nt * 8;
            float b0 = bias[col], b1 = bias[col + 1];
#pragma unroll
            for (int half = 0; half < 2; half++) {
                int row = r0 + mt * 16 + half * 8;
                float v0 = acc[mt][nt][2 * half + 0] + b0;
                float v1 = acc[mt][nt][2 * half + 1] + b1;
                if (RELU) { v0 = fmaxf(v0, 0.f); v1 = fmaxf(v1, 0.f); }
                size_t off = (size_t)row * N + col;
                if (!SPLIT) {
                    float2 w = {v0, v1};
                    *(float2*)(Cf + off) = w;
                } else {
                    uint32_t hi, lo;
                    psplit2(v0, v1, hi, lo);
                    *(uint32_t*)(Ch + off) = hi;
                    *(uint32_t*)(Cl + off) = lo;
                }
            }
        }
    }
}

// ======================= HMMA banded flash attention =======================
#define AP     72
#define AROWB  (AP * 2)
#define QTILEB (128 * AROWB)
#define ATILEB (64 * AROWB)
#define ASTGB  (4 * ATILEB)
#define ATT_SMEM (2 * QTILEB + 2 * ASTGB)

__global__ void __launch_bounds__(256, 1)
k_attn(const __nv_bfloat16* __restrict__ qh, const __nv_bfloat16* __restrict__ ql,
       __nv_bfloat16* __restrict__ ah, __nv_bfloat16* __restrict__ al)
{
    extern __shared__ char asm_[];
    const uint32_t sbase = smem_to_u32(asm_);
    const uint32_t Qh_s = sbase, Ql_s = sbase + QTILEB;
    const uint32_t stg0 = sbase + 2 * QTILEB;

    const int tid = threadIdx.x;
    const int lane = tid & 31;
    const int w = tid >> 5;
    const int Qb = blockIdx.x, h = blockIdx.y, b = blockIdx.z;
    const int nch = min(16, 2 * Qb + 3);
    const size_t rstr = 3 * DM;
    const size_t rowoff0 = (size_t)(b * SEQ) * rstr + h * HD;

#pragma unroll
    for (int i = 0; i < 8; i++) {
        int lin = i * 256 + tid;
        int hl = lin >> 10, loc = lin & 1023;
        int r = loc >> 3, p = loc & 7;
        const __nv_bfloat16* src = (hl ? ql : qh) + rowoff0 + (size_t)(Qb * 128 + r) * rstr + p * 8;
        cpa16((hl ? Ql_s : Qh_s) + r * AROWB + p * 16, src);
    }
#pragma unroll
    for (int i = 0; i < 8; i++) {
        int lin = i * 256 + tid;
        int t = lin >> 9, loc = lin & 511;
        int r = loc >> 3, p = loc & 7;
        const __nv_bfloat16* src = ((t & 1) ? ql : qh) + rowoff0
            + (size_t)(0 + r) * rstr + ((t < 2) ? DM : 2 * DM) + p * 8;
        cpa16(stg0 + t * ATILEB + r * AROWB + p * 16, src);
    }
    asm volatile("cp.async.commit_group;" ::: "memory");
    asm volatile("cp.async.wait_group 0;" ::: "memory");
    __syncthreads();

    uint32_t qfh[4][4], qfl[4][4];
    {
        uint32_t qaddr = ((w * 16 + (lane & 15)) * AROWB) + (lane >> 4) * 16;
#pragma unroll
        for (int ks = 0; ks < 4; ks++) {
            ldsm_x4(qfh[ks], Qh_s + qaddr + ks * 32);
            ldsm_x4(qfl[ks], Ql_s + qaddr + ks * 32);
        }
    }

    float oacc[8][4];
#pragma unroll
    for (int nt = 0; nt < 8; nt++)
#pragma unroll
        for (int i = 0; i < 4; i++) oacc[nt][i] = 0.f;
    float m0 = -1e30f, m1 = -1e30f, l0 = 0.f, l1 = 0.f;

    const int q0 = Qb * 128 + w * 16 + (lane >> 2);
    const int lim0 = q0 + WIN, lim1 = q0 + 8 + WIN;
    const int limw = Qb * 128 + w * 16 + 15 + WIN;     // warp's max allowed j
    const uint32_t kfoff = ((lane & 7) * AROWB) + ((lane >> 3) & 1) * 16;
    const uint32_t vfoff = ((lane & 15) * AROWB);

    for (int c = 0; c < nch; c++) {
        if (c > 0) {
            asm volatile("cp.async.wait_group 0;" ::: "memory");
            __syncthreads();
        }
        if (c + 1 < nch) {
            uint32_t stg = stg0 + ((c + 1) & 1) * ASTGB;
#pragma unroll
            for (int i = 0; i < 8; i++) {
                int lin = i * 256 + tid;
                int t = lin >> 9, loc = lin & 511;
                int r = loc >> 3, p = loc & 7;
                const __nv_bfloat16* src = ((t & 1) ? ql : qh) + rowoff0
                    + (size_t)((c + 1) * 64 + r) * rstr + ((t < 2) ? DM : 2 * DM) + p * 8;
                cpa16(stg + t * ATILEB + r * AROWB + p * 16, src);
            }
        }
        asm volatile("cp.async.commit_group;" ::: "memory");

        if (c * 64 > limw) continue;      // whole chunk masked for this warp

        const uint32_t stg = stg0 + (c & 1) * ASTGB;
        const uint32_t Kh_s = stg, Kl_s = stg + ATILEB;
        const uint32_t Vh_s = stg + 2 * ATILEB, Vl_s = stg + 3 * ATILEB;

        float sacc[8][4];
#pragma unroll
        for (int nt = 0; nt < 8; nt++)
#pragma unroll
            for (int i = 0; i < 4; i++) sacc[nt][i] = 0.f;
#pragma unroll
        for (int ks = 0; ks < 4; ks++) {
#pragma unroll
            for (int nt = 0; nt < 8; nt++) {
                uint32_t kh[2], kl[2];
                uint32_t off = nt * 8 * AROWB + kfoff + ks * 32;
                ldsm_x2(kh, Kh_s + off);
                ldsm_x2(kl, Kl_s + off);
                mma16816(sacc[nt], qfh[ks], kh);
                mma16816(sacc[nt], qfh[ks], kl);
                mma16816(sacc[nt], qfl[ks], kh);
            }
        }

        const float scale = 0.125f;
        float mc0 = -1e30f, mc1 = -1e30f;
        const bool domask = (c >= 2 * Qb + 1);
        const int jb = c * 64 + 2 * (lane & 3);
#pragma unroll
        for (int nt = 0; nt < 8; nt++) {
            int j0 = jb + nt * 8, j1 = j0 + 1;
            float s0 = sacc[nt][0] * scale, s1 = sacc[nt][1] * scale;
            float s2 = sacc[nt][2] * scale, s3 = sacc[nt][3] * scale;
            if (domask) {
                if (j0 > lim0) s0 = -1e30f;
                if (j1 > lim0) s1 = -1e30f;
                if (j0 > lim1) s2 = -1e30f;
                if (j1 > lim1) s3 = -1e30f;
            }
            sacc[nt][0] = s0; sacc[nt][1] = s1; sacc[nt][2] = s2; sacc[nt][3] = s3;
            mc0 = fmaxf(mc0, fmaxf(s0, s1));
            mc1 = fmaxf(mc1, fmaxf(s2, s3));
        }
        mc0 = fmaxf(mc0, __shfl_xor_sync(~0u, mc0, 1));
        mc0 = fmaxf(mc0, __shfl_xor_sync(~0u, mc0, 2));
        mc1 = fmaxf(mc1, __shfl_xor_sync(~0u, mc1, 1));
        mc1 = fmaxf(mc1, __shfl_xor_sync(~0u, mc1, 2));
        float m0n = fmaxf(m0, mc0), m1n = fmaxf(m1, mc1);
        float a0 = __expf(m0 - m0n), a1 = __expf(m1 - m1n);
        l0 *= a0; l1 *= a1;
#pragma unroll
        for (int nt = 0; nt < 8; nt++) {
            oacc[nt][0] *= a0; oacc[nt][1] *= a0;
            oacc[nt][2] *= a1; oacc[nt][3] *= a1;
        }
#pragma unroll
        for (int nt = 0; nt < 8; nt++) {
            float p0 = __expf(sacc[nt][0] - m0n), p1 = __expf(sacc[nt][1] - m0n);
            float p2 = __expf(sacc[nt][2] - m1n), p3 = __expf(sacc[nt][3] - m1n);
            sacc[nt][0] = p0; sacc[nt][1] = p1; sacc[nt][2] = p2; sacc[nt][3] = p3;
            l0 += p0 + p1; l1 += p2 + p3;
        }
        m0 = m0n; m1 = m1n;

#pragma unroll
        for (int kk = 0; kk < 4; kk++) {
            uint32_t pah[4], pal[4];
            psplit2(sacc[2*kk][0],   sacc[2*kk][1],   pah[0], pal[0]);
            psplit2(sacc[2*kk][2],   sacc[2*kk][3],   pah[1], pal[1]);
            psplit2(sacc[2*kk+1][0], sacc[2*kk+1][1], pah[2], pal[2]);
            psplit2(sacc[2*kk+1][2], sacc[2*kk+1][3], pah[3], pal[3]);
#pragma unroll
            for (int nt = 0; nt < 8; nt++) {
                uint32_t vh[2], vl[2];
                uint32_t off = kk * 16 * AROWB + vfoff + nt * 16;
                ldsm_x2t(vh, Vh_s + off);
                ldsm_x2t(vl, Vl_s + off);
                mma16816(oacc[nt], pah, vh);
                mma16816(oacc[nt], pah, vl);
                mma16816(oacc[nt], pal, vh);
            }
        }
    }

    l0 += __shfl_xor_sync(~0u, l0, 1); l0 += __shfl_xor_sync(~0u, l0, 2);
    l1 += __shfl_xor_sync(~0u, l1, 1); l1 += __shfl_xor_sync(~0u, l1, 2);
    float inv0 = 1.0f / l0, inv1 = 1.0f / l1;
    size_t orow0 = (size_t)(b * SEQ + q0) * DM + h * HD;
    size_t orow1 = orow0 + (size_t)8 * DM;
    int cbase = 2 * (lane & 3);
#pragma unroll
    for (int nt = 0; nt < 8; nt++) {
        int col = cbase + nt * 8;
        uint32_t hi, lo;
        psplit2(oacc[nt][0] * inv0, oacc[nt][1] * inv0, hi, lo);
        *(uint32_t*)(ah + orow0 + col) = hi;
        *(uint32_t*)(al + orow0 + col) = lo;
        psplit2(oacc[nt][2] * inv1, oacc[nt][3] * inv1, hi, lo);
        *(uint32_t*)(ah + orow1 + col) = hi;
        *(uint32_t*)(al + orow1 + col) = lo;
    }
}

// ======================= LayerNorm(resid + delta) -> fp32 + hi/lo =======================
__global__ void __launch_bounds__(256)
k_ln(const float* __restrict__ resid, const float* __restrict__ delta,
     const float* __restrict__ gamma, const float* __restrict__ beta,
     float* __restrict__ out, __nv_bfloat16* __restrict__ oh, __nv_bfloat16* __restrict__ ol)
{
    __shared__ float red[8];
    const int row = blockIdx.x;
    const int t = threadIdx.x;
    const float* rp = resid + (size_t)row * DM;
    const float* dp = delta + (size_t)row * DM;

    float4 rv = *(const float4*)(rp + t * 4);
    float4 dv = *(const float4*)(dp + t * 4);
    float v[4] = {rv.x + dv.x, rv.y + dv.y, rv.z + dv.z, rv.w + dv.w};

    float s = v[0] + v[1] + v[2] + v[3];
#pragma unroll
    for (int off = 16; off; off >>= 1) s += __shfl_xor_sync(~0u, s, off);
    if ((t & 31) == 0) red[t >> 5] = s;
    __syncthreads();
    if (t < 8) {
        float x = red[t];
#pragma unroll
        for (int off = 4; off; off >>= 1) x += __shfl_xor_sync(0xffu, x, off);
        if (t == 0) red[0] = x;
    }
    __syncthreads();
    float mu = red[0] * (1.0f / DM);
    __syncthreads();

    float vs = 0.f;
#pragma unroll
    for (int i = 0; i < 4; i++) { float d = v[i] - mu; vs += d * d; }
#pragma unroll
    for (int off = 16; off; off >>= 1) vs += __shfl_xor_sync(~0u, vs, off);
    if ((t & 31) == 0) red[t >> 5] = vs;
    __syncthreads();
    if (t < 8) {
        float x = red[t];
#pragma unroll
        for (int off = 4; off; off >>= 1) x += __shfl_xor_sync(0xffu, x, off);
        if (t == 0) red[0] = x;
    }
    __syncthreads();
    float rstd = rsqrtf(red[0] * (1.0f / DM) + 1e-5f);

    float4 g4 = *(const float4*)(gamma + t * 4);
    float4 b4 = *(const float4*)(beta  + t * 4);
    float w[4];
    w[0] = (v[0] - mu) * rstd * g4.x + b4.x;
    w[1] = (v[1] - mu) * rstd * g4.y + b4.y;
    w[2] = (v[2] - mu) * rstd * g4.z + b4.z;
    w[3] = (v[3] - mu) * rstd * g4.w + b4.w;
    float4 wf = {w[0], w[1], w[2], w[3]};
    *(float4*)(out + (size_t)row * DM + t * 4) = wf;
    split4(w, oh + (size_t)row * DM + t * 4, ol + (size_t)row * DM + t * 4);
}

// ======================= host driver =======================
extern "C" void kernel_launch(void* const* d_in, const int* in_sizes, int n_in,
                              void* d_out, int out_size)
{
    const float* x    = (const float*)d_in[0];
    const float* Wqkv = (const float*)d_in[1];
    const float* bqkv = (const float*)d_in[2];
    const float* Wo   = (const float*)d_in[3];
    const float* bo   = (const float*)d_in[4];
    const float* W1   = (const float*)d_in[5];
    const float* b1   = (const float*)d_in[6];
    const float* W2   = (const float*)d_in[7];
    const float* b2   = (const float*)d_in[8];
    const float* g1   = (const float*)d_in[9];
    const float* be1  = (const float*)d_in[10];
    const float* g2   = (const float*)d_in[11];
    const float* be2  = (const float*)d_in[12];
    float* out = (float*)d_out;

    float *p_xb, *p_delta;
    __nv_bfloat16 *p_xh, *p_xl, *p_qkvh, *p_qkvl, *p_ah, *p_al, *p_fh, *p_fl;
    __nv_bfloat16 *p_wqh, *p_wql, *p_woh, *p_wol, *p_w1h, *p_w1l, *p_w2h, *p_w2l;
    cudaGetSymbolAddress((void**)&p_xb,  g_xb);
    cudaGetSymbolAddress((void**)&p_delta, g_delta);
    cudaGetSymbolAddress((void**)&p_xh,  g_xh);
    cudaGetSymbolAddress((void**)&p_xl,  g_xl);
    cudaGetSymbolAddress((void**)&p_qkvh, g_qkvh);
    cudaGetSymbolAddress((void**)&p_qkvl, g_qkvl);
    cudaGetSymbolAddress((void**)&p_ah,  g_ah);
    cudaGetSymbolAddress((void**)&p_al,  g_al);
    cudaGetSymbolAddress((void**)&p_fh,  g_fh);
    cudaGetSymbolAddress((void**)&p_fl,  g_fl);
    cudaGetSymbolAddress((void**)&p_wqh, g_wqh);
    cudaGetSymbolAddress((void**)&p_wql, g_wql);
    cudaGetSymbolAddress((void**)&p_woh, g_woh);
    cudaGetSymbolAddress((void**)&p_wol, g_wol);
    cudaGetSymbolAddress((void**)&p_w1h, g_w1h);
    cudaGetSymbolAddress((void**)&p_w1l, g_w1l);
    cudaGetSymbolAddress((void**)&p_w2h, g_w2h);
    cudaGetSymbolAddress((void**)&p_w2l, g_w2l);

    cudaFuncSetAttribute(k_tgemm<0,0>, cudaFuncAttributeMaxDynamicSharedMemorySize, TG_SMEM);
    cudaFuncSetAttribute(k_tgemm<0,1>, cudaFuncAttributeMaxDynamicSharedMemorySize, TG_SMEM);
    cudaFuncSetAttribute(k_tgemm<1,1>, cudaFuncAttributeMaxDynamicSharedMemorySize, TG_SMEM);
    cudaFuncSetAttribute(k_attn, cudaFuncAttributeMaxDynamicSharedMemorySize, ATT_SMEM);

    {
        int ntot = (NL * 3 * DM * DM + NL * DM * DM + NL * DFF * DM + NL * DM * DFF) / 4;
        k_split_all<<<(ntot + 255) / 256, 256>>>(Wqkv, Wo, W1, W2,
            p_wqh, p_wql, p_woh, p_wol, p_w1h, p_w1l, p_w2h, p_w2l);
    }

    const int nElem = MTOT * DM;
    k_in<<<(nElem + 255) / 256, 256>>>(x, p_xb, p_xh, p_xl);

    for (int l = 0; l < NL; l++) {
        k_tgemm<0,1><<<dim3(3 * DM / 128, MTOT / 256), 256, TG_SMEM>>>(
            p_xh, p_xl,
            p_wqh + (size_t)l * 3 * DM * DM, p_wql + (size_t)l * 3 * DM * DM,
            bqkv + (size_t)l * 3 * DM,
            nullptr, p_qkvh, p_qkvl, MTOT, 3 * DM, DM);

        k_attn<<<dim3(SEQ / 128, NH, BATCH), 256, ATT_SMEM>>>(p_qkvh, p_qkvl, p_ah, p_al);

        k_tgemm<0,0><<<dim3(DM / 128, MTOT / 256), 256, TG_SMEM>>>(
            p_ah, p_al,
            p_woh + (size_t)l * DM * DM, p_wol + (size_t)l * DM * DM,
            bo + (size_t)l * DM,
            p_delta, nullptr, nullptr, MTOT, DM, DM);

        k_ln<<<MTOT, 256>>>(p_xb, p_delta, g1 + (size_t)l * DM, be1 + (size_t)l * DM,
                            p_xb, p_xh, p_xl);

        k_tgemm<1,1><<<dim3(DFF / 128, MTOT / 256), 256, TG_SMEM>>>(
            p_xh, p_xl,
            p_w1h + (size_t)l * DFF * DM, p_w1l + (size_t)l * DFF * DM,
            b1 + (size_t)l * DFF,
            nullptr, p_fh, p_fl, MTOT, DFF, DM);

        k_tgemm<0,0><<<dim3(DM / 128, MTOT / 256), 256, TG_SMEM>>>(
            p_fh, p_fl,
            p_w2h + (size_t)l * DM * DFF, p_w2l + (size_t)l * DM * DFF,
            b2 + (size_t)l * DM,
            p_delta, nullptr, nullptr, MTOT, DM, DFF);

        k_ln<<<MTOT, 256>>>(p_xb, p_delta, g2 + (size_t)l * DM, be2 + (size_t)l * DM,
                            p_xb, p_xh, p_xl);
    }

    k_out<<<(nElem + 255) / 256, 256>>>(p_xb, out);
}